// round 1
// baseline (speedup 1.0000x reference)
#include <cuda_runtime.h>
#include <cstdint>

// Problem constants
#define BATCH 4
#define SEQ   2048
#define EDIM  1024
#define QN    4
#define HN    16
#define DH    64
#define NTOK  (BATCH*SEQ)        // 8192
#define QCOLS (QN*EDIM)          // 4096

// Scratch (static __device__ globals — no runtime allocation allowed)
__device__ float g_q[(size_t)NTOK * QCOLS];   // 8192 x 4096
__device__ float g_k[(size_t)NTOK * EDIM];    // 8192 x 1024
__device__ float g_v[(size_t)NTOK * EDIM];    // 8192 x 1024
__device__ float g_y[(size_t)NTOK * EDIM];    // (B,H,S,D) flat == (B,S,E) flat

typedef unsigned long long u64;

__device__ __forceinline__ u64 pk2(float lo, float hi) {
    u64 r; asm("mov.b64 %0, {%1, %2};" : "=l"(r) : "f"(lo), "f"(hi)); return r;
}
__device__ __forceinline__ void upk2(u64 v, float& lo, float& hi) {
    asm("mov.b64 {%0, %1}, %2;" : "=f"(lo), "=f"(hi) : "l"(v));
}
__device__ __forceinline__ void ffma2(u64& d, u64 a, u64 b) {
    asm("fma.rn.f32x2 %0, %1, %2, %0;" : "+l"(d) : "l"(a), "l"(b));
}

// C[m,n] = sum_k A[m,k] * W[n,k] + bias[n]
// A: MxK row-major, W: NxK row-major. BM=BN=128, BK=16, 256 threads, 8x8/thread.
// Inner product issued as fma.rn.f32x2 (FFMA2) to hit the full fp32 fma rate.
__global__ void __launch_bounds__(256, 2)
sgemm_tn(const float* __restrict__ A, const float* __restrict__ W,
         const float* __restrict__ bias, float* __restrict__ C,
         int M, int N, int K)
{
    const int BM = 128, BN = 128, BK = 16;
    __shared__ __align__(16) float As[BK][BM + 4];
    __shared__ __align__(16) float Bs[BK][BN + 4];

    const int bm = blockIdx.y * BM;
    const int bn = blockIdx.x * BN;
    const int tid = threadIdx.x;
    const int tr = tid >> 4;           // 0..15
    const int tc = tid & 15;           // 0..15
    const int row0 = tr * 8;
    const int col0 = tc * 8;

    u64 acc[8][4];
#pragma unroll
    for (int i = 0; i < 8; i++)
#pragma unroll
        for (int j = 0; j < 4; j++) acc[i][j] = 0ULL;

    for (int kt = 0; kt < K; kt += BK) {
        // Load A tile (128x16) as float4, store transposed into As[k][m]
#pragma unroll
        for (int l = 0; l < 2; l++) {
            int f4 = tid + l * 256;          // 0..511
            int r  = f4 >> 2;                // 0..127
            int c4 = f4 & 3;                 // 0..3
            float4 v = *(const float4*)(A + (size_t)(bm + r) * K + kt + c4 * 4);
            As[c4 * 4 + 0][r] = v.x;
            As[c4 * 4 + 1][r] = v.y;
            As[c4 * 4 + 2][r] = v.z;
            As[c4 * 4 + 3][r] = v.w;
        }
        // Load W tile (128x16) the same way
#pragma unroll
        for (int l = 0; l < 2; l++) {
            int f4 = tid + l * 256;
            int r  = f4 >> 2;
            int c4 = f4 & 3;
            float4 v = *(const float4*)(W + (size_t)(bn + r) * K + kt + c4 * 4);
            Bs[c4 * 4 + 0][r] = v.x;
            Bs[c4 * 4 + 1][r] = v.y;
            Bs[c4 * 4 + 2][r] = v.z;
            Bs[c4 * 4 + 3][r] = v.w;
        }
        __syncthreads();

#pragma unroll
        for (int k = 0; k < BK; k++) {
            float4 a0 = *(const float4*)&As[k][row0];
            float4 a1 = *(const float4*)&As[k][row0 + 4];
            float4 b0 = *(const float4*)&Bs[k][col0];
            float4 b1 = *(const float4*)&Bs[k][col0 + 4];
            float a[8] = {a0.x, a0.y, a0.z, a0.w, a1.x, a1.y, a1.z, a1.w};
            u64 bb[4];
            bb[0] = pk2(b0.x, b0.y);
            bb[1] = pk2(b0.z, b0.w);
            bb[2] = pk2(b1.x, b1.y);
            bb[3] = pk2(b1.z, b1.w);
#pragma unroll
            for (int i = 0; i < 8; i++) {
                u64 aa = pk2(a[i], a[i]);
#pragma unroll
                for (int j = 0; j < 4; j++) ffma2(acc[i][j], aa, bb[j]);
            }
        }
        __syncthreads();
    }

    // Epilogue: unpack, add bias, vectorized store
#pragma unroll
    for (int i = 0; i < 8; i++) {
        float out[8];
#pragma unroll
        for (int j = 0; j < 4; j++) upk2(acc[i][j], out[2 * j], out[2 * j + 1]);
        size_t base = (size_t)(bm + row0 + i) * N + bn + col0;
        float4 o0, o1;
        o0.x = out[0] + bias[bn + col0 + 0];
        o0.y = out[1] + bias[bn + col0 + 1];
        o0.z = out[2] + bias[bn + col0 + 2];
        o0.w = out[3] + bias[bn + col0 + 3];
        o1.x = out[4] + bias[bn + col0 + 4];
        o1.y = out[5] + bias[bn + col0 + 5];
        o1.z = out[6] + bias[bn + col0 + 6];
        o1.w = out[7] + bias[bn + col0 + 7];
        *(float4*)(C + base)     = o0;
        *(float4*)(C + base + 4) = o1;
    }
}

// Per-token head-mixing attention.
// For each token (b,s):
//   scores[qq,h,g] = (1/8) * dot(q[qq,h,:], k[g,:])       (d over 64)
//   probs = softmax over g (16 heads)
//   psum[h,g] = sum_qq probs[qq,h,g]
//   y[b,h,s,d] = sum_g psum[h,g] * v[g,d]
// Writing y in (B,H,S,D) order reproduces the torch transpose+view exactly.
__global__ void __launch_bounds__(256)
attn_kernel(const float* __restrict__ gq, const float* __restrict__ gk,
            const float* __restrict__ gv, float* __restrict__ gy)
{
    const int tok = blockIdx.x;       // 0..8191
    const int t = threadIdx.x;        // 0..255

    __shared__ __align__(16) float qs[QN][HN][DH];  // 16 KB
    __shared__ float ks[HN][DH + 1];                 // padded vs bank conflicts
    __shared__ __align__(16) float vs[HN][DH];
    __shared__ float sc[QN][HN][HN];
    __shared__ float ps[HN][HN];

    // Load q (4096 floats, vectorized)
    {
        const float4* qg = (const float4*)(gq + (size_t)tok * QCOLS);
        float4* qsf = (float4*)&qs[0][0][0];
#pragma unroll
        for (int l = 0; l < 4; l++) qsf[t + l * 256] = qg[t + l * 256];
    }
    // Load k (padded) and v
    {
        const float4* kg = (const float4*)(gk + (size_t)tok * EDIM);
        const float4* vg = (const float4*)(gv + (size_t)tok * EDIM);
        float4 kv = kg[t];
        int g = (t * 4) >> 6, d = (t * 4) & 63;
        ks[g][d + 0] = kv.x; ks[g][d + 1] = kv.y;
        ks[g][d + 2] = kv.z; ks[g][d + 3] = kv.w;
        ((float4*)&vs[0][0])[t] = vg[t];
    }
    __syncthreads();

    // Scores: 1024 entries, 4 per thread
    const float scale = 0.125f;
#pragma unroll
    for (int l = 0; l < 4; l++) {
        int e = t + l * 256;
        int qq = e >> 8, h = (e >> 4) & 15, g = e & 15;
        const float* qp = qs[qq][h];
        const float* kp = ks[g];
        float s_ = 0.f;
#pragma unroll
        for (int d = 0; d < DH; d++) s_ = fmaf(qp[d], kp[d], s_);
        sc[qq][h][g] = s_ * scale;
    }
    __syncthreads();

    // Softmax over g per (qq,h): 64 rows, one thread each
    if (t < 64) {
        int qq = t >> 4, h = t & 15;
        float* row = sc[qq][h];
        float m = row[0];
#pragma unroll
        for (int g = 1; g < 16; g++) m = fmaxf(m, row[g]);
        float ssum = 0.f;
#pragma unroll
        for (int g = 0; g < 16; g++) { float ex = __expf(row[g] - m); row[g] = ex; ssum += ex; }
        float inv = 1.f / ssum;
#pragma unroll
        for (int g = 0; g < 16; g++) row[g] *= inv;
    }
    __syncthreads();

    // psum[h,g] = sum over qq
    {
        int h = t >> 4, g = t & 15;
        ps[h][g] = sc[0][h][g] + sc[1][h][g] + sc[2][h][g] + sc[3][h][g];
    }
    __syncthreads();

    // y[h,d] = sum_g ps[h,g] * v[g,d]  -> write at (b,h,s,d)
    const int b = tok >> 11, s = tok & 2047;
#pragma unroll
    for (int l = 0; l < 4; l++) {
        int e = t + l * 256;
        int h = e >> 6, d = e & 63;
        float acc = 0.f;
#pragma unroll
        for (int g = 0; g < 16; g++) acc = fmaf(ps[h][g], vs[g][d], acc);
        gy[(((size_t)b * HN + h) * SEQ + s) * DH + d] = acc;
    }
}

extern "C" void kernel_launch(void* const* d_in, const int* in_sizes, int n_in,
                              void* d_out, int out_size)
{
    const float* x  = (const float*)d_in[0];
    const float* Wq = (const float*)d_in[1];   // (Q,E,E) == (4096,1024) stacked
    const float* bq = (const float*)d_in[2];   // (4096)
    const float* Wk = (const float*)d_in[3];
    const float* bk = (const float*)d_in[4];
    const float* Wv = (const float*)d_in[5];
    const float* bv = (const float*)d_in[6];
    const float* Wo = (const float*)d_in[7];
    const float* bo = (const float*)d_in[8];
    float* out = (float*)d_out;
    (void)in_sizes; (void)n_in; (void)out_size;

    float *gq, *gk, *gv, *gy;
    cudaGetSymbolAddress((void**)&gq, g_q);
    cudaGetSymbolAddress((void**)&gk, g_k);
    cudaGetSymbolAddress((void**)&gv, g_v);
    cudaGetSymbolAddress((void**)&gy, g_y);

    dim3 blk(256);

    // 1) Projections: X @ W^T + b
    sgemm_tn<<<dim3(QCOLS / 128, NTOK / 128), blk>>>(x, Wq, bq, gq, NTOK, QCOLS, EDIM);
    sgemm_tn<<<dim3(EDIM / 128,  NTOK / 128), blk>>>(x, Wk, bk, gk, NTOK, EDIM, EDIM);
    sgemm_tn<<<dim3(EDIM / 128,  NTOK / 128), blk>>>(x, Wv, bv, gv, NTOK, EDIM, EDIM);

    // 2) Per-token attention over heads -> g_y in (B,H,S,D) == (B,S,E) flat
    attn_kernel<<<NTOK, blk>>>(gq, gk, gv, gy);

    // 3) Output projection: Y @ Wo^T + bo
    sgemm_tn<<<dim3(EDIM / 128, NTOK / 128), blk>>>(gy, Wo, bo, out, NTOK, EDIM, EDIM);
}

// round 3
// speedup vs baseline: 2.5503x; 2.5503x over previous
#include <cuda_runtime.h>
#include <cuda_bf16.h>
#include <cstdint>

#define BATCH 4
#define SEQ   2048
#define EDIM  1024
#define QN    4
#define HN    16
#define DH    64
#define NTOK  (BATCH*SEQ)        // 8192
#define QCOLS (QN*EDIM)          // 4096

// ------------------------- scratch (static, no runtime alloc) ---------------
__device__ float g_q[(size_t)NTOK * QCOLS];
__device__ float g_k[(size_t)NTOK * EDIM];
__device__ float g_v[(size_t)NTOK * EDIM];
__device__ __nv_bfloat16 g_xh[(size_t)NTOK * EDIM];
__device__ __nv_bfloat16 g_xl[(size_t)NTOK * EDIM];
__device__ __nv_bfloat16 g_yh[(size_t)NTOK * EDIM];   // attn out (B,H,S,D) flat
__device__ __nv_bfloat16 g_yl[(size_t)NTOK * EDIM];
__device__ __nv_bfloat16 g_wqh[(size_t)QCOLS * EDIM];
__device__ __nv_bfloat16 g_wql[(size_t)QCOLS * EDIM];
__device__ __nv_bfloat16 g_wkh[(size_t)EDIM * EDIM];
__device__ __nv_bfloat16 g_wkl[(size_t)EDIM * EDIM];
__device__ __nv_bfloat16 g_wvh[(size_t)EDIM * EDIM];
__device__ __nv_bfloat16 g_wvl[(size_t)EDIM * EDIM];
__device__ __nv_bfloat16 g_woh[(size_t)EDIM * EDIM];
__device__ __nv_bfloat16 g_wol[(size_t)EDIM * EDIM];

// ------------------------- helpers ------------------------------------------
__device__ __forceinline__ uint32_t smem_to_u32(const void* p) {
    uint32_t a;
    asm("{ .reg .u64 t; cvta.to.shared.u64 t, %1; cvt.u32.u64 %0, t; }" : "=r"(a) : "l"(p));
    return a;
}
__device__ __forceinline__ void cp16(uint32_t dst, const void* src) {
    asm volatile("cp.async.cg.shared.global [%0], [%1], 16;" :: "r"(dst), "l"(src));
}
__device__ __forceinline__ void cp_commit() { asm volatile("cp.async.commit_group;" ::: "memory"); }
__device__ __forceinline__ void cp_wait0()  { asm volatile("cp.async.wait_group 0;"  ::: "memory"); }
__device__ __forceinline__ void ldx4(uint32_t* r, uint32_t addr) {
    asm volatile("ldmatrix.sync.aligned.m8n8.x4.shared.b16 {%0,%1,%2,%3}, [%4];"
        : "=r"(r[0]), "=r"(r[1]), "=r"(r[2]), "=r"(r[3]) : "r"(addr));
}
__device__ __forceinline__ void mma16816(float* d, const uint32_t* a, const uint32_t* b) {
    asm volatile("mma.sync.aligned.m16n8k16.row.col.f32.bf16.bf16.f32 "
        "{%0,%1,%2,%3}, {%4,%5,%6,%7}, {%8,%9}, {%0,%1,%2,%3};"
        : "+f"(d[0]), "+f"(d[1]), "+f"(d[2]), "+f"(d[3])
        : "r"(a[0]), "r"(a[1]), "r"(a[2]), "r"(a[3]), "r"(b[0]), "r"(b[1]));
}

// ------------------------- split fp32 -> bf16 hi/lo -------------------------
__global__ void __launch_bounds__(256)
split_kernel(const float* __restrict__ src, __nv_bfloat16* __restrict__ hi,
             __nv_bfloat16* __restrict__ lo, int n4)
{
    int i = blockIdx.x * 256 + threadIdx.x;
    if (i >= n4) return;
    float4 v = ((const float4*)src)[i];
    float vv[4] = {v.x, v.y, v.z, v.w};
    __nv_bfloat162 h2[2], l2[2];
#pragma unroll
    for (int j = 0; j < 2; j++) {
        __nv_bfloat16 h0 = __float2bfloat16(vv[2 * j]);
        __nv_bfloat16 h1 = __float2bfloat16(vv[2 * j + 1]);
        __nv_bfloat16 l0 = __float2bfloat16(vv[2 * j] - __bfloat162float(h0));
        __nv_bfloat16 l1 = __float2bfloat16(vv[2 * j + 1] - __bfloat162float(h1));
        h2[j] = __nv_bfloat162(h0, h1);
        l2[j] = __nv_bfloat162(l0, l1);
    }
    ((uint2*)hi)[i] = *(uint2*)h2;
    ((uint2*)lo)[i] = *(uint2*)l2;
}

// ------------------------- HMMA bf16x3 GEMM ---------------------------------
// C[m,n] = sum_k A[m,k]*W[n,k] + bias[n], via mma.sync m16n8k16 bf16.
// 128x128 CTA tile, BK=32, 8 warps (warp tile 64x32), double-buffered cp.async.
#define GBK   32
#define ROWB  80                  // 64B data + 16B pad (conflict-free ldmatrix)
#define TILEB (128 * ROWB)        // 10240 B
#define STAGEB (4 * TILEB)        // Ah, Al, Wh, Wl
#define GSMEM (2 * STAGEB)        // 81920 B

__global__ void __launch_bounds__(256)
gemm_mma(const __nv_bfloat16* __restrict__ Ah, const __nv_bfloat16* __restrict__ Al,
         const __nv_bfloat16* __restrict__ Wh, const __nv_bfloat16* __restrict__ Wl,
         const float* __restrict__ bias, float* __restrict__ C, int N, int K)
{
    extern __shared__ __align__(16) char smem[];
    const uint32_t sb = smem_to_u32(smem);
    const int tid = threadIdx.x;
    const int lane = tid & 31;
    const int warp = tid >> 5;
    const int bm = blockIdx.y * 128;
    const int bn = blockIdx.x * 128;
    const int wm0 = (warp & 1) * 64;     // warp row offset in tile
    const int wn0 = (warp >> 1) * 32;    // warp col offset in tile

    float acc[4][4][4];
#pragma unroll
    for (int i = 0; i < 4; i++)
#pragma unroll
        for (int j = 0; j < 4; j++)
#pragma unroll
            for (int r = 0; r < 4; r++) acc[i][j][r] = 0.f;

    const int lrow = tid >> 2;     // 0..63 (two passes cover 128 rows)
    const int lq   = tid & 3;      // 16B quarter within 64B row

    auto load_chunk = [&](int stage, int ck) {
        const __nv_bfloat16* srcs[4] = {Ah, Al, Wh, Wl};
        const uint32_t stb = sb + stage * STAGEB;
#pragma unroll
        for (int t = 0; t < 4; t++) {
            const __nv_bfloat16* S = srcs[t];
            const int rbase = (t < 2) ? bm : bn;
            const uint32_t tb = stb + t * TILEB;
#pragma unroll
            for (int l = 0; l < 2; l++) {
                int row = lrow + l * 64;
                uint32_t dst = tb + row * ROWB + lq * 16;
                const void* src = S + (size_t)(rbase + row) * K + ck * GBK + lq * 8;
                cp16(dst, src);
            }
        }
    };

    auto compute = [&](int stage) {
        const uint32_t tAh = sb + stage * STAGEB;
        const uint32_t tAl = tAh + TILEB;
        const uint32_t tWh = tAh + 2 * TILEB;
        const uint32_t tWl = tAh + 3 * TILEB;
#pragma unroll
        for (int ks = 0; ks < 2; ks++) {
            uint32_t ah[4][4], al[4][4], bh[2][4], bl[2][4];
            const uint32_t kb = ks * 32;   // byte offset of k16 step
#pragma unroll
            for (int rb = 0; rb < 4; rb++) {
                uint32_t off = (uint32_t)(wm0 + rb * 16 + (lane & 15)) * ROWB
                             + kb + ((lane >> 4) << 4);
                ldx4(ah[rb], tAh + off);
                ldx4(al[rb], tAl + off);
            }
#pragma unroll
            for (int hb = 0; hb < 2; hb++) {
                uint32_t off = (uint32_t)(wn0 + hb * 16 + (lane & 7) + ((lane >> 4) << 3)) * ROWB
                             + kb + (((lane >> 3) & 1) << 4);
                ldx4(bh[hb], tWh + off);
                ldx4(bl[hb], tWl + off);
            }
#pragma unroll
            for (int rb = 0; rb < 4; rb++) {
#pragma unroll
                for (int nb = 0; nb < 4; nb++) {
                    const uint32_t* ph = &bh[nb >> 1][(nb & 1) * 2];
                    const uint32_t* pl = &bl[nb >> 1][(nb & 1) * 2];
                    mma16816(acc[rb][nb], ah[rb], ph);
                    mma16816(acc[rb][nb], ah[rb], pl);
                    mma16816(acc[rb][nb], al[rb], ph);
                }
            }
        }
    };

    const int nchunk = K / GBK;
    load_chunk(0, 0);
    cp_commit();
    for (int c = 0; c < nchunk; c++) {
        cp_wait0();
        __syncthreads();
        if (c + 1 < nchunk) { load_chunk((c + 1) & 1, c + 1); cp_commit(); }
        compute(c & 1);
        __syncthreads();
    }

    // epilogue: D fragment -> C + bias
#pragma unroll
    for (int rb = 0; rb < 4; rb++) {
#pragma unroll
        for (int nb = 0; nb < 4; nb++) {
            int row = bm + wm0 + rb * 16 + (lane >> 2);
            int col = bn + wn0 + nb * 8 + (lane & 3) * 2;
            float b0 = bias[col], b1 = bias[col + 1];
            float2 v0 = {acc[rb][nb][0] + b0, acc[rb][nb][1] + b1};
            float2 v1 = {acc[rb][nb][2] + b0, acc[rb][nb][3] + b1};
            *(float2*)(C + (size_t)row * N + col)       = v0;
            *(float2*)(C + (size_t)(row + 8) * N + col) = v1;
        }
    }
}

// ------------------------- per-token head-mixing attention ------------------
__global__ void __launch_bounds__(256)
attn_kernel(const float* __restrict__ gq, const float* __restrict__ gk,
            const float* __restrict__ gv, __nv_bfloat16* __restrict__ yh,
            __nv_bfloat16* __restrict__ yl)
{
    const int tok = blockIdx.x;
    const int t = threadIdx.x;

    __shared__ __align__(16) float qs[QN][HN][DH];
    __shared__ float ks[HN][DH + 1];
    __shared__ __align__(16) float vs[HN][DH];
    __shared__ float sc[QN][HN][HN];
    __shared__ float ps[HN][HN];

    {
        const float4* qg = (const float4*)(gq + (size_t)tok * QCOLS);
        float4* qsf = (float4*)&qs[0][0][0];
#pragma unroll
        for (int l = 0; l < 4; l++) qsf[t + l * 256] = qg[t + l * 256];
    }
    {
        const float4* kg = (const float4*)(gk + (size_t)tok * EDIM);
        const float4* vg = (const float4*)(gv + (size_t)tok * EDIM);
        float4 kv = kg[t];
        int g = (t * 4) >> 6, d = (t * 4) & 63;
        ks[g][d + 0] = kv.x; ks[g][d + 1] = kv.y;
        ks[g][d + 2] = kv.z; ks[g][d + 3] = kv.w;
        ((float4*)&vs[0][0])[t] = vg[t];
    }
    __syncthreads();

    const float scale = 0.125f;
#pragma unroll
    for (int l = 0; l < 4; l++) {
        int e = t + l * 256;
        int qq = e >> 8, h = (e >> 4) & 15, g = e & 15;
        const float* qp = qs[qq][h];
        const float* kp = ks[g];
        float s_ = 0.f;
#pragma unroll
        for (int d = 0; d < DH; d++) s_ = fmaf(qp[d], kp[d], s_);
        sc[qq][h][g] = s_ * scale;
    }
    __syncthreads();

    if (t < 64) {
        int qq = t >> 4, h = t & 15;
        float* row = sc[qq][h];
        float m = row[0];
#pragma unroll
        for (int g = 1; g < 16; g++) m = fmaxf(m, row[g]);
        float ssum = 0.f;
#pragma unroll
        for (int g = 0; g < 16; g++) { float ex = __expf(row[g] - m); row[g] = ex; ssum += ex; }
        float inv = 1.f / ssum;
#pragma unroll
        for (int g = 0; g < 16; g++) row[g] *= inv;
    }
    __syncthreads();

    {
        int h = t >> 4, g = t & 15;
        ps[h][g] = sc[0][h][g] + sc[1][h][g] + sc[2][h][g] + sc[3][h][g];
    }
    __syncthreads();

    const int b = tok >> 11, s = tok & 2047;
#pragma unroll
    for (int l = 0; l < 4; l++) {
        int e = t + l * 256;
        int h = e >> 6, d = e & 63;
        float acc = 0.f;
#pragma unroll
        for (int g = 0; g < 16; g++) acc = fmaf(ps[h][g], vs[g][d], acc);
        size_t oi = (((size_t)b * HN + h) * SEQ + s) * DH + d;
        __nv_bfloat16 hh = __float2bfloat16(acc);
        __nv_bfloat16 ll = __float2bfloat16(acc - __bfloat162float(hh));
        yh[oi] = hh;
        yl[oi] = ll;
    }
}

// ------------------------- launch -------------------------------------------
extern "C" void kernel_launch(void* const* d_in, const int* in_sizes, int n_in,
                              void* d_out, int out_size)
{
    const float* x  = (const float*)d_in[0];
    const float* Wq = (const float*)d_in[1];
    const float* bq = (const float*)d_in[2];
    const float* Wk = (const float*)d_in[3];
    const float* bk = (const float*)d_in[4];
    const float* Wv = (const float*)d_in[5];
    const float* bv = (const float*)d_in[6];
    const float* Wo = (const float*)d_in[7];
    const float* bo = (const float*)d_in[8];
    float* out = (float*)d_out;
    (void)in_sizes; (void)n_in; (void)out_size;

    float *gq, *gk, *gv;
    __nv_bfloat16 *xh, *xl, *yh, *yl, *wqh, *wql, *wkh, *wkl, *wvh, *wvl, *woh, *wol;
    cudaGetSymbolAddress((void**)&gq, g_q);
    cudaGetSymbolAddress((void**)&gk, g_k);
    cudaGetSymbolAddress((void**)&gv, g_v);
    cudaGetSymbolAddress((void**)&xh, g_xh);
    cudaGetSymbolAddress((void**)&xl, g_xl);
    cudaGetSymbolAddress((void**)&yh, g_yh);
    cudaGetSymbolAddress((void**)&yl, g_yl);
    cudaGetSymbolAddress((void**)&wqh, g_wqh);
    cudaGetSymbolAddress((void**)&wql, g_wql);
    cudaGetSymbolAddress((void**)&wkh, g_wkh);
    cudaGetSymbolAddress((void**)&wkl, g_wkl);
    cudaGetSymbolAddress((void**)&wvh, g_wvh);
    cudaGetSymbolAddress((void**)&wvl, g_wvl);
    cudaGetSymbolAddress((void**)&woh, g_woh);
    cudaGetSymbolAddress((void**)&wol, g_wol);

    cudaFuncSetAttribute(gemm_mma, cudaFuncAttributeMaxDynamicSharedMemorySize, GSMEM);

    // 1) fp32 -> bf16 hi/lo splits
    split_kernel<<<(NTOK * EDIM / 4 + 255) / 256, 256>>>(x, xh, xl, NTOK * EDIM / 4);
    split_kernel<<<(QCOLS * EDIM / 4 + 255) / 256, 256>>>(Wq, wqh, wql, QCOLS * EDIM / 4);
    split_kernel<<<(EDIM * EDIM / 4 + 255) / 256, 256>>>(Wk, wkh, wkl, EDIM * EDIM / 4);
    split_kernel<<<(EDIM * EDIM / 4 + 255) / 256, 256>>>(Wv, wvh, wvl, EDIM * EDIM / 4);
    split_kernel<<<(EDIM * EDIM / 4 + 255) / 256, 256>>>(Wo, woh, wol, EDIM * EDIM / 4);

    // 2) projections on tensor cores (HMMA)
    gemm_mma<<<dim3(QCOLS / 128, NTOK / 128), 256, GSMEM>>>(xh, xl, wqh, wql, bq, gq, QCOLS, EDIM);
    gemm_mma<<<dim3(EDIM / 128,  NTOK / 128), 256, GSMEM>>>(xh, xl, wkh, wkl, bk, gk, EDIM, EDIM);
    gemm_mma<<<dim3(EDIM / 128,  NTOK / 128), 256, GSMEM>>>(xh, xl, wvh, wvl, bv, gv, EDIM, EDIM);

    // 3) per-token attention -> y (bf16 hi/lo, (B,H,S,D) flat == (B,S,E) flat)
    attn_kernel<<<NTOK, 256>>>(gq, gk, gv, yh, yl);

    // 4) output projection
    gemm_mma<<<dim3(EDIM / 128, NTOK / 128), 256, GSMEM>>>(yh, yl, woh, wol, bo, out, EDIM, EDIM);
}

// round 4
// speedup vs baseline: 3.5086x; 1.3758x over previous
#include <cuda_runtime.h>
#include <cuda_fp16.h>
#include <cstdint>

#define BATCH 4
#define SEQ   2048
#define EDIM  1024
#define QN    4
#define HN    16
#define DH    64
#define NTOK  (BATCH*SEQ)        // 8192
#define QCOLS (QN*EDIM)          // 4096

// ------------------------- scratch (static, no runtime alloc) ---------------
__device__ __half g_q[(size_t)NTOK * QCOLS];    // q projections (fp16)
__device__ float  g_k[(size_t)NTOK * EDIM];
__device__ float  g_v[(size_t)NTOK * EDIM];
__device__ __half g_xf[(size_t)NTOK * EDIM];    // x in fp16
__device__ __half g_y[(size_t)NTOK * EDIM];     // attn out (B,H,S,D) flat, fp16
__device__ __half g_wqh[(size_t)QCOLS * EDIM];
__device__ __half g_wql[(size_t)QCOLS * EDIM];
__device__ __half g_wkh[(size_t)EDIM * EDIM];
__device__ __half g_wkl[(size_t)EDIM * EDIM];
__device__ __half g_wvh[(size_t)EDIM * EDIM];
__device__ __half g_wvl[(size_t)EDIM * EDIM];
__device__ __half g_woh[(size_t)EDIM * EDIM];
__device__ __half g_wol[(size_t)EDIM * EDIM];

// ------------------------- helpers ------------------------------------------
__device__ __forceinline__ uint32_t smem_to_u32(const void* p) {
    uint32_t a;
    asm("{ .reg .u64 t; cvta.to.shared.u64 t, %1; cvt.u32.u64 %0, t; }" : "=r"(a) : "l"(p));
    return a;
}
__device__ __forceinline__ void cp16(uint32_t dst, const void* src) {
    asm volatile("cp.async.cg.shared.global [%0], [%1], 16;" :: "r"(dst), "l"(src));
}
__device__ __forceinline__ void cp_commit() { asm volatile("cp.async.commit_group;" ::: "memory"); }
__device__ __forceinline__ void cp_wait0()  { asm volatile("cp.async.wait_group 0;"  ::: "memory"); }
__device__ __forceinline__ void cp_wait1()  { asm volatile("cp.async.wait_group 1;"  ::: "memory"); }
__device__ __forceinline__ void ldx4(uint32_t* r, uint32_t addr) {
    asm volatile("ldmatrix.sync.aligned.m8n8.x4.shared.b16 {%0,%1,%2,%3}, [%4];"
        : "=r"(r[0]), "=r"(r[1]), "=r"(r[2]), "=r"(r[3]) : "r"(addr));
}
__device__ __forceinline__ void mma16816(float* d, const uint32_t* a, const uint32_t* b) {
    asm volatile("mma.sync.aligned.m16n8k16.row.col.f32.f16.f16.f32 "
        "{%0,%1,%2,%3}, {%4,%5,%6,%7}, {%8,%9}, {%0,%1,%2,%3};"
        : "+f"(d[0]), "+f"(d[1]), "+f"(d[2]), "+f"(d[3])
        : "r"(a[0]), "r"(a[1]), "r"(a[2]), "r"(a[3]), "r"(b[0]), "r"(b[1]));
}

// ------------------------- conversion kernels -------------------------------
__global__ void __launch_bounds__(256)
conv_half(const float* __restrict__ src, __half* __restrict__ dst, int n4)
{
    int i = blockIdx.x * 256 + threadIdx.x;
    if (i >= n4) return;
    float4 v = ((const float4*)src)[i];
    __half2 h[2];
    h[0] = __floats2half2_rn(v.x, v.y);
    h[1] = __floats2half2_rn(v.z, v.w);
    ((uint2*)dst)[i] = *(uint2*)h;
}

__global__ void __launch_bounds__(256)
split_half(const float* __restrict__ src, __half* __restrict__ hi,
           __half* __restrict__ lo, int n4)
{
    int i = blockIdx.x * 256 + threadIdx.x;
    if (i >= n4) return;
    float4 v = ((const float4*)src)[i];
    float vv[4] = {v.x, v.y, v.z, v.w};
    __half hh[4], ll[4];
#pragma unroll
    for (int j = 0; j < 4; j++) {
        hh[j] = __float2half_rn(vv[j]);
        ll[j] = __float2half_rn(vv[j] - __half2float(hh[j]));
    }
    ((uint2*)hi)[i] = *(uint2*)hh;
    ((uint2*)lo)[i] = *(uint2*)ll;
}

// ------------------------- HMMA fp16x2 GEMM ---------------------------------
// C[m,n] = sum_k A[m,k]*(Wh[n,k]+Wl[n,k]) + bias[n], mma.sync m16n8k16 fp16.
// 128x128 CTA tile, BK=32, 8 warps (warp tile 64x32), 3-stage cp.async.
#define GBK    32
#define ROWB   80                  // 64B data + 16B pad (conflict-free ldmatrix)
#define TILEB  (128 * ROWB)        // 10240 B
#define STAGEB (3 * TILEB)         // A, Wh, Wl = 30720 B
#define NSTG   3
#define GSMEM  (NSTG * STAGEB)     // 92160 B

template <typename OutT>
__global__ void __launch_bounds__(256, 2)
gemm_f16x2(const __half* __restrict__ A, const __half* __restrict__ Wh,
           const __half* __restrict__ Wl, const float* __restrict__ bias,
           OutT* __restrict__ C, int N, int K)
{
    extern __shared__ __align__(16) char smem[];
    const uint32_t sb = smem_to_u32(smem);
    const int tid = threadIdx.x;
    const int lane = tid & 31;
    const int warp = tid >> 5;
    const int bm = blockIdx.y * 128;
    const int bn = blockIdx.x * 128;
    const int wm0 = (warp & 1) * 64;
    const int wn0 = (warp >> 1) * 32;

    float acc[4][4][4];
#pragma unroll
    for (int i = 0; i < 4; i++)
#pragma unroll
        for (int j = 0; j < 4; j++)
#pragma unroll
            for (int r = 0; r < 4; r++) acc[i][j][r] = 0.f;

    const int lrow = tid >> 2;     // 0..63
    const int lq   = tid & 3;      // 16B quarter of 64B row

    auto load_chunk = [&](int stage, int ck) {
        const __half* srcs[3] = {A, Wh, Wl};
        const uint32_t stb = sb + stage * STAGEB;
#pragma unroll
        for (int t = 0; t < 3; t++) {
            const __half* S = srcs[t];
            const int rbase = (t == 0) ? bm : bn;
            const uint32_t tb = stb + t * TILEB;
#pragma unroll
            for (int l = 0; l < 2; l++) {
                int row = lrow + l * 64;
                uint32_t dst = tb + row * ROWB + lq * 16;
                const void* src = S + (size_t)(rbase + row) * K + ck * GBK + lq * 8;
                cp16(dst, src);
            }
        }
    };

    auto compute = [&](int stage) {
        const uint32_t tA  = sb + stage * STAGEB;
        const uint32_t tWh = tA + TILEB;
        const uint32_t tWl = tA + 2 * TILEB;
#pragma unroll
        for (int ks = 0; ks < 2; ks++) {
            uint32_t a[4][4], bh[2][4], bl[2][4];
            const uint32_t kb = ks * 32;
#pragma unroll
            for (int rb = 0; rb < 4; rb++) {
                uint32_t off = (uint32_t)(wm0 + rb * 16 + (lane & 15)) * ROWB
                             + kb + ((lane >> 4) << 4);
                ldx4(a[rb], tA + off);
            }
#pragma unroll
            for (int hb = 0; hb < 2; hb++) {
                uint32_t off = (uint32_t)(wn0 + hb * 16 + (lane & 7) + ((lane >> 4) << 3)) * ROWB
                             + kb + (((lane >> 3) & 1) << 4);
                ldx4(bh[hb], tWh + off);
                ldx4(bl[hb], tWl + off);
            }
#pragma unroll
            for (int rb = 0; rb < 4; rb++) {
#pragma unroll
                for (int nb = 0; nb < 4; nb++) {
                    mma16816(acc[rb][nb], a[rb], &bh[nb >> 1][(nb & 1) * 2]);
                    mma16816(acc[rb][nb], a[rb], &bl[nb >> 1][(nb & 1) * 2]);
                }
            }
        }
    };

    const int nchunk = K / GBK;
    load_chunk(0, 0); cp_commit();
    load_chunk(1, 1); cp_commit();
    for (int c = 0; c < nchunk; c++) {
        if (c == nchunk - 1) cp_wait0(); else cp_wait1();
        __syncthreads();
        if (c + 2 < nchunk) { load_chunk((c + 2) % NSTG, c + 2); cp_commit(); }
        compute(c % NSTG);
    }

    // epilogue
#pragma unroll
    for (int rb = 0; rb < 4; rb++) {
#pragma unroll
        for (int nb = 0; nb < 4; nb++) {
            int row = bm + wm0 + rb * 16 + (lane >> 2);
            int col = bn + wn0 + nb * 8 + (lane & 3) * 2;
            float b0 = bias[col], b1 = bias[col + 1];
            float o0 = acc[rb][nb][0] + b0, o1 = acc[rb][nb][1] + b1;
            float o2 = acc[rb][nb][2] + b0, o3 = acc[rb][nb][3] + b1;
            if constexpr (sizeof(OutT) == 2) {
                __half2 h0 = __floats2half2_rn(o0, o1);
                __half2 h1 = __floats2half2_rn(o2, o3);
                *(__half2*)((__half*)C + (size_t)row * N + col)       = h0;
                *(__half2*)((__half*)C + (size_t)(row + 8) * N + col) = h1;
            } else {
                float2 v0 = {o0, o1}, v1 = {o2, o3};
                *(float2*)((float*)C + (size_t)row * N + col)       = v0;
                *(float2*)((float*)C + (size_t)(row + 8) * N + col) = v1;
            }
        }
    }
}

// ------------------------- per-token head-mixing attention ------------------
__global__ void __launch_bounds__(256)
attn_kernel(const __half* __restrict__ gq, const float* __restrict__ gk,
            const float* __restrict__ gv, __half* __restrict__ gy)
{
    const int tok = blockIdx.x;
    const int t = threadIdx.x;

    __shared__ __align__(16) float qs[QN * HN * DH];   // 4096 floats
    __shared__ float ks[HN][DH + 1];
    __shared__ __align__(16) float vs[HN][DH];
    __shared__ float sc[QN][HN][HN];
    __shared__ float ps[HN][HN];

    // load q (fp16 -> fp32 smem)
    {
        const uint4* qg = (const uint4*)(gq + (size_t)tok * QCOLS);
#pragma unroll
        for (int l = 0; l < 2; l++) {
            uint4 p = qg[t + l * 256];
            const __half2* hp = (const __half2*)&p;
            float* dst = qs + (t + l * 256) * 8;
#pragma unroll
            for (int j = 0; j < 4; j++) {
                float2 f = __half22float2(hp[j]);
                dst[2 * j] = f.x; dst[2 * j + 1] = f.y;
            }
        }
    }
    // load k (padded) and v
    {
        const float4* kg = (const float4*)(gk + (size_t)tok * EDIM);
        const float4* vg = (const float4*)(gv + (size_t)tok * EDIM);
        float4 kv = kg[t];
        int g = (t * 4) >> 6, d = (t * 4) & 63;
        ks[g][d + 0] = kv.x; ks[g][d + 1] = kv.y;
        ks[g][d + 2] = kv.z; ks[g][d + 3] = kv.w;
        ((float4*)&vs[0][0])[t] = vg[t];
    }
    __syncthreads();

    const float scale = 0.125f;
#pragma unroll
    for (int l = 0; l < 4; l++) {
        int e = t + l * 256;
        int qq = e >> 8, h = (e >> 4) & 15, g = e & 15;
        const float* qp = qs + (qq * HN + h) * DH;
        const float* kp = ks[g];
        float s_ = 0.f;
#pragma unroll
        for (int d = 0; d < DH; d++) s_ = fmaf(qp[d], kp[d], s_);
        sc[qq][h][g] = s_ * scale;
    }
    __syncthreads();

    if (t < 64) {
        int qq = t >> 4, h = t & 15;
        float* row = sc[qq][h];
        float m = row[0];
#pragma unroll
        for (int g = 1; g < 16; g++) m = fmaxf(m, row[g]);
        float ssum = 0.f;
#pragma unroll
        for (int g = 0; g < 16; g++) { float ex = __expf(row[g] - m); row[g] = ex; ssum += ex; }
        float inv = 1.f / ssum;
#pragma unroll
        for (int g = 0; g < 16; g++) row[g] *= inv;
    }
    __syncthreads();

    {
        int h = t >> 4, g = t & 15;
        ps[h][g] = sc[0][h][g] + sc[1][h][g] + sc[2][h][g] + sc[3][h][g];
    }
    __syncthreads();

    // y[h,d0..d0+3], 4 consecutive d per thread -> packed half2 x2 store
    const int b = tok >> 11, s = tok & 2047;
    {
        int h = t >> 4;              // (t*4)>>6
        int d0 = (t * 4) & 63;
        float o[4];
#pragma unroll
        for (int j = 0; j < 4; j++) o[j] = 0.f;
#pragma unroll
        for (int g = 0; g < 16; g++) {
            float p = ps[h][g];
#pragma unroll
            for (int j = 0; j < 4; j++) o[j] = fmaf(p, vs[g][d0 + j], o[j]);
        }
        __half2 h0 = __floats2half2_rn(o[0], o[1]);
        __half2 h1 = __floats2half2_rn(o[2], o[3]);
        size_t oi = (((size_t)b * HN + h) * SEQ + s) * DH + d0;
        *(__half2*)(gy + oi)     = h0;
        *(__half2*)(gy + oi + 2) = h1;
    }
}

// ------------------------- launch -------------------------------------------
extern "C" void kernel_launch(void* const* d_in, const int* in_sizes, int n_in,
                              void* d_out, int out_size)
{
    const float* x  = (const float*)d_in[0];
    const float* Wq = (const float*)d_in[1];
    const float* bq = (const float*)d_in[2];
    const float* Wk = (const float*)d_in[3];
    const float* bk = (const float*)d_in[4];
    const float* Wv = (const float*)d_in[5];
    const float* bv = (const float*)d_in[6];
    const float* Wo = (const float*)d_in[7];
    const float* bo = (const float*)d_in[8];
    float* out = (float*)d_out;
    (void)in_sizes; (void)n_in; (void)out_size;

    __half *gq, *xf, *gy, *wqh, *wql, *wkh, *wkl, *wvh, *wvl, *woh, *wol;
    float *gk, *gv;
    cudaGetSymbolAddress((void**)&gq, g_q);
    cudaGetSymbolAddress((void**)&gk, g_k);
    cudaGetSymbolAddress((void**)&gv, g_v);
    cudaGetSymbolAddress((void**)&xf, g_xf);
    cudaGetSymbolAddress((void**)&gy, g_y);
    cudaGetSymbolAddress((void**)&wqh, g_wqh);
    cudaGetSymbolAddress((void**)&wql, g_wql);
    cudaGetSymbolAddress((void**)&wkh, g_wkh);
    cudaGetSymbolAddress((void**)&wkl, g_wkl);
    cudaGetSymbolAddress((void**)&wvh, g_wvh);
    cudaGetSymbolAddress((void**)&wvl, g_wvl);
    cudaGetSymbolAddress((void**)&woh, g_woh);
    cudaGetSymbolAddress((void**)&wol, g_wol);

    cudaFuncSetAttribute(gemm_f16x2<float>,  cudaFuncAttributeMaxDynamicSharedMemorySize, GSMEM);
    cudaFuncSetAttribute(gemm_f16x2<__half>, cudaFuncAttributeMaxDynamicSharedMemorySize, GSMEM);

    // 1) conversions / weight splits
    conv_half<<<(NTOK * EDIM / 4 + 255) / 256, 256>>>(x, xf, NTOK * EDIM / 4);
    split_half<<<(QCOLS * EDIM / 4 + 255) / 256, 256>>>(Wq, wqh, wql, QCOLS * EDIM / 4);
    split_half<<<(EDIM * EDIM / 4 + 255) / 256, 256>>>(Wk, wkh, wkl, EDIM * EDIM / 4);
    split_half<<<(EDIM * EDIM / 4 + 255) / 256, 256>>>(Wv, wvh, wvl, EDIM * EDIM / 4);
    split_half<<<(EDIM * EDIM / 4 + 255) / 256, 256>>>(Wo, woh, wol, EDIM * EDIM / 4);

    // 2) projections (tensor cores, fp16 2-product)
    gemm_f16x2<__half><<<dim3(QCOLS / 128, NTOK / 128), 256, GSMEM>>>(xf, wqh, wql, bq, gq, QCOLS, EDIM);
    gemm_f16x2<float ><<<dim3(EDIM / 128,  NTOK / 128), 256, GSMEM>>>(xf, wkh, wkl, bk, gk, EDIM, EDIM);
    gemm_f16x2<float ><<<dim3(EDIM / 128,  NTOK / 128), 256, GSMEM>>>(xf, wvh, wvl, bv, gv, EDIM, EDIM);

    // 3) per-token attention -> y fp16 ((B,H,S,D) flat == (B,S,E) flat)
    attn_kernel<<<NTOK, 256>>>(gq, gk, gv, gy);

    // 4) output projection
    gemm_f16x2<float><<<dim3(EDIM / 128, NTOK / 128), 256, GSMEM>>>(gy, woh, wol, bo, out, EDIM, EDIM);
}

// round 5
// speedup vs baseline: 5.4698x; 1.5590x over previous
#include <cuda_runtime.h>
#include <cuda_fp16.h>
#include <cstdint>

#define BATCH 4
#define SEQ   2048
#define EDIM  1024
#define QN    4
#define HN    16
#define DH    64
#define NTOK  (BATCH*SEQ)        // 8192
#define QCOLS (QN*EDIM)          // 4096

// ------------------------- scratch (static, no runtime alloc) ---------------
__device__ __half g_q[(size_t)NTOK * QCOLS];    // q projections (fp16)
__device__ __half g_k[(size_t)NTOK * EDIM];
__device__ __half g_v[(size_t)NTOK * EDIM];
__device__ __half g_xf[(size_t)NTOK * EDIM];    // x in fp16
__device__ __half g_y[(size_t)NTOK * EDIM];     // attn out (B,H,S,D) flat, fp16
__device__ __half g_wq[(size_t)QCOLS * EDIM];
__device__ __half g_wk[(size_t)EDIM * EDIM];
__device__ __half g_wv[(size_t)EDIM * EDIM];
__device__ __half g_wo[(size_t)EDIM * EDIM];

// ------------------------- helpers ------------------------------------------
__device__ __forceinline__ uint32_t smem_to_u32(const void* p) {
    uint32_t a;
    asm("{ .reg .u64 t; cvta.to.shared.u64 t, %1; cvt.u32.u64 %0, t; }" : "=r"(a) : "l"(p));
    return a;
}
__device__ __forceinline__ void cp16(uint32_t dst, const void* src) {
    asm volatile("cp.async.cg.shared.global [%0], [%1], 16;" :: "r"(dst), "l"(src));
}
__device__ __forceinline__ void cp_commit() { asm volatile("cp.async.commit_group;" ::: "memory"); }
__device__ __forceinline__ void cp_wait0()  { asm volatile("cp.async.wait_group 0;"  ::: "memory"); }
__device__ __forceinline__ void cp_wait1()  { asm volatile("cp.async.wait_group 1;"  ::: "memory"); }
__device__ __forceinline__ void ldx4(uint32_t* r, uint32_t addr) {
    asm volatile("ldmatrix.sync.aligned.m8n8.x4.shared.b16 {%0,%1,%2,%3}, [%4];"
        : "=r"(r[0]), "=r"(r[1]), "=r"(r[2]), "=r"(r[3]) : "r"(addr));
}
__device__ __forceinline__ void mma16816(float* d, const uint32_t* a, const uint32_t* b) {
    asm volatile("mma.sync.aligned.m16n8k16.row.col.f32.f16.f16.f32 "
        "{%0,%1,%2,%3}, {%4,%5,%6,%7}, {%8,%9}, {%0,%1,%2,%3};"
        : "+f"(d[0]), "+f"(d[1]), "+f"(d[2]), "+f"(d[3])
        : "r"(a[0]), "r"(a[1]), "r"(a[2]), "r"(a[3]), "r"(b[0]), "r"(b[1]));
}

// ------------------------- conversion kernel --------------------------------
__global__ void __launch_bounds__(256)
conv_half(const float* __restrict__ src, __half* __restrict__ dst, int n4)
{
    int i = blockIdx.x * 256 + threadIdx.x;
    if (i >= n4) return;
    float4 v = ((const float4*)src)[i];
    __half2 h[2];
    h[0] = __floats2half2_rn(v.x, v.y);
    h[1] = __floats2half2_rn(v.z, v.w);
    ((uint2*)dst)[i] = *(uint2*)h;
}

// ------------------------- HMMA fp16 GEMM -----------------------------------
// C[m,n] = sum_k A[m,k]*W[n,k] + bias[n], mma.sync m16n8k16 fp16, fp32 accum.
// 128x128 CTA tile, BK=32, 8 warps (warp tile 64x32), 3-stage cp.async.
#define GBK    32
#define ROWB   80                  // 64B data + 16B pad (conflict-free ldmatrix)
#define TILEB  (128 * ROWB)        // 10240 B
#define STAGEB (2 * TILEB)         // A, W = 20480 B
#define NSTG   3
#define GSMEM  (NSTG * STAGEB)     // 61440 B

template <typename OutT>
__global__ void __launch_bounds__(256, 2)
gemm_f16(const __half* __restrict__ A, const __half* __restrict__ W,
         const float* __restrict__ bias, OutT* __restrict__ C, int N, int K)
{
    extern __shared__ __align__(16) char smem[];
    const uint32_t sb = smem_to_u32(smem);
    const int tid = threadIdx.x;
    const int lane = tid & 31;
    const int warp = tid >> 5;
    const int bm = blockIdx.y * 128;
    const int bn = blockIdx.x * 128;
    const int wm0 = (warp & 1) * 64;
    const int wn0 = (warp >> 1) * 32;

    float acc[4][4][4];
#pragma unroll
    for (int i = 0; i < 4; i++)
#pragma unroll
        for (int j = 0; j < 4; j++)
#pragma unroll
            for (int r = 0; r < 4; r++) acc[i][j][r] = 0.f;

    const int lrow = tid >> 2;     // 0..63
    const int lq   = tid & 3;      // 16B quarter of 64B row

    auto load_chunk = [&](int stage, int ck) {
        const uint32_t stb = sb + stage * STAGEB;
#pragma unroll
        for (int l = 0; l < 2; l++) {
            int row = lrow + l * 64;
            uint32_t dst = stb + row * ROWB + lq * 16;
            cp16(dst, A + (size_t)(bm + row) * K + ck * GBK + lq * 8);
            cp16(dst + TILEB, W + (size_t)(bn + row) * K + ck * GBK + lq * 8);
        }
    };

    auto compute = [&](int stage) {
        const uint32_t tA = sb + stage * STAGEB;
        const uint32_t tW = tA + TILEB;
#pragma unroll
        for (int ks = 0; ks < 2; ks++) {
            uint32_t a[4][4], b[2][4];
            const uint32_t kb = ks * 32;
#pragma unroll
            for (int rb = 0; rb < 4; rb++) {
                uint32_t off = (uint32_t)(wm0 + rb * 16 + (lane & 15)) * ROWB
                             + kb + ((lane >> 4) << 4);
                ldx4(a[rb], tA + off);
            }
#pragma unroll
            for (int hb = 0; hb < 2; hb++) {
                uint32_t off = (uint32_t)(wn0 + hb * 16 + (lane & 7) + ((lane >> 4) << 3)) * ROWB
                             + kb + (((lane >> 3) & 1) << 4);
                ldx4(b[hb], tW + off);
            }
#pragma unroll
            for (int rb = 0; rb < 4; rb++) {
#pragma unroll
                for (int nb = 0; nb < 4; nb++) {
                    mma16816(acc[rb][nb], a[rb], &b[nb >> 1][(nb & 1) * 2]);
                }
            }
        }
    };

    const int nchunk = K / GBK;
    load_chunk(0, 0); cp_commit();
    load_chunk(1, 1); cp_commit();
    for (int c = 0; c < nchunk; c++) {
        if (c == nchunk - 1) cp_wait0(); else cp_wait1();
        __syncthreads();
        if (c + 2 < nchunk) { load_chunk((c + 2) % NSTG, c + 2); cp_commit(); }
        compute(c % NSTG);
    }

    // epilogue
#pragma unroll
    for (int rb = 0; rb < 4; rb++) {
#pragma unroll
        for (int nb = 0; nb < 4; nb++) {
            int row = bm + wm0 + rb * 16 + (lane >> 2);
            int col = bn + wn0 + nb * 8 + (lane & 3) * 2;
            float b0 = bias[col], b1 = bias[col + 1];
            float o0 = acc[rb][nb][0] + b0, o1 = acc[rb][nb][1] + b1;
            float o2 = acc[rb][nb][2] + b0, o3 = acc[rb][nb][3] + b1;
            if constexpr (sizeof(OutT) == 2) {
                __half2 h0 = __floats2half2_rn(o0, o1);
                __half2 h1 = __floats2half2_rn(o2, o3);
                *(__half2*)((__half*)C + (size_t)row * N + col)       = h0;
                *(__half2*)((__half*)C + (size_t)(row + 8) * N + col) = h1;
            } else {
                float2 v0 = {o0, o1}, v1 = {o2, o3};
                *(float2*)((float*)C + (size_t)row * N + col)       = v0;
                *(float2*)((float*)C + (size_t)(row + 8) * N + col) = v1;
            }
        }
    }
}

// ------------------------- per-token head-mixing attention ------------------
__global__ void __launch_bounds__(256)
attn_kernel(const __half* __restrict__ gq, const __half* __restrict__ gk,
            const __half* __restrict__ gv, __half* __restrict__ gy)
{
    const int tok = blockIdx.x;
    const int t = threadIdx.x;

    __shared__ __align__(16) float qs[QN * HN * DH];   // 4096 floats
    __shared__ float ks[HN][DH + 1];
    __shared__ __align__(16) float vs[HN][DH];
    __shared__ float sc[QN][HN][HN];
    __shared__ float ps[HN][HN];

    // load q (fp16 -> fp32 smem)
    {
        const uint4* qg = (const uint4*)(gq + (size_t)tok * QCOLS);
#pragma unroll
        for (int l = 0; l < 2; l++) {
            uint4 p = qg[t + l * 256];
            const __half2* hp = (const __half2*)&p;
            float* dst = qs + (t + l * 256) * 8;
#pragma unroll
            for (int j = 0; j < 4; j++) {
                float2 f = __half22float2(hp[j]);
                dst[2 * j] = f.x; dst[2 * j + 1] = f.y;
            }
        }
    }
    // load k (threads 0..127) and v (threads 128..255), 8 halfs per thread
    if (t < 128) {
        uint4 p = ((const uint4*)(gk + (size_t)tok * EDIM))[t];
        const __half2* hp = (const __half2*)&p;
        int g = t >> 3, d = (t * 8) & 63;
#pragma unroll
        for (int j = 0; j < 4; j++) {
            float2 f = __half22float2(hp[j]);
            ks[g][d + 2 * j] = f.x; ks[g][d + 2 * j + 1] = f.y;
        }
    } else {
        int tt = t - 128;
        uint4 p = ((const uint4*)(gv + (size_t)tok * EDIM))[tt];
        const __half2* hp = (const __half2*)&p;
        int g = tt >> 3, d = (tt * 8) & 63;
#pragma unroll
        for (int j = 0; j < 4; j++) {
            float2 f = __half22float2(hp[j]);
            vs[g][d + 2 * j] = f.x; vs[g][d + 2 * j + 1] = f.y;
        }
    }
    __syncthreads();

    const float scale = 0.125f;
#pragma unroll
    for (int l = 0; l < 4; l++) {
        int e = t + l * 256;
        int qq = e >> 8, h = (e >> 4) & 15, g = e & 15;
        const float* qp = qs + (qq * HN + h) * DH;
        const float* kp = ks[g];
        float s_ = 0.f;
#pragma unroll
        for (int d = 0; d < DH; d++) s_ = fmaf(qp[d], kp[d], s_);
        sc[qq][h][g] = s_ * scale;
    }
    __syncthreads();

    if (t < 64) {
        int qq = t >> 4, h = t & 15;
        float* row = sc[qq][h];
        float m = row[0];
#pragma unroll
        for (int g = 1; g < 16; g++) m = fmaxf(m, row[g]);
        float ssum = 0.f;
#pragma unroll
        for (int g = 0; g < 16; g++) { float ex = __expf(row[g] - m); row[g] = ex; ssum += ex; }
        float inv = 1.f / ssum;
#pragma unroll
        for (int g = 0; g < 16; g++) row[g] *= inv;
    }
    __syncthreads();

    {
        int h = t >> 4, g = t & 15;
        ps[h][g] = sc[0][h][g] + sc[1][h][g] + sc[2][h][g] + sc[3][h][g];
    }
    __syncthreads();

    // y[h,d0..d0+3], 4 consecutive d per thread -> packed half2 x2 store
    const int b = tok >> 11, s = tok & 2047;
    {
        int h = t >> 4;
        int d0 = (t * 4) & 63;
        float o[4];
#pragma unroll
        for (int j = 0; j < 4; j++) o[j] = 0.f;
#pragma unroll
        for (int g = 0; g < 16; g++) {
            float p = ps[h][g];
#pragma unroll
            for (int j = 0; j < 4; j++) o[j] = fmaf(p, vs[g][d0 + j], o[j]);
        }
        __half2 h0 = __floats2half2_rn(o[0], o[1]);
        __half2 h1 = __floats2half2_rn(o[2], o[3]);
        size_t oi = (((size_t)b * HN + h) * SEQ + s) * DH + d0;
        *(__half2*)(gy + oi)     = h0;
        *(__half2*)(gy + oi + 2) = h1;
    }
}

// ------------------------- launch -------------------------------------------
extern "C" void kernel_launch(void* const* d_in, const int* in_sizes, int n_in,
                              void* d_out, int out_size)
{
    const float* x  = (const float*)d_in[0];
    const float* Wq = (const float*)d_in[1];
    const float* bq = (const float*)d_in[2];
    const float* Wk = (const float*)d_in[3];
    const float* bk = (const float*)d_in[4];
    const float* Wv = (const float*)d_in[5];
    const float* bv = (const float*)d_in[6];
    const float* Wo = (const float*)d_in[7];
    const float* bo = (const float*)d_in[8];
    float* out = (float*)d_out;
    (void)in_sizes; (void)n_in; (void)out_size;

    __half *gq, *gk, *gv, *xf, *gy, *wq, *wk, *wv, *wo;
    cudaGetSymbolAddress((void**)&gq, g_q);
    cudaGetSymbolAddress((void**)&gk, g_k);
    cudaGetSymbolAddress((void**)&gv, g_v);
    cudaGetSymbolAddress((void**)&xf, g_xf);
    cudaGetSymbolAddress((void**)&gy, g_y);
    cudaGetSymbolAddress((void**)&wq, g_wq);
    cudaGetSymbolAddress((void**)&wk, g_wk);
    cudaGetSymbolAddress((void**)&wv, g_wv);
    cudaGetSymbolAddress((void**)&wo, g_wo);

    cudaFuncSetAttribute(gemm_f16<float>,  cudaFuncAttributeMaxDynamicSharedMemorySize, GSMEM);
    cudaFuncSetAttribute(gemm_f16<__half>, cudaFuncAttributeMaxDynamicSharedMemorySize, GSMEM);

    // 1) fp32 -> fp16 conversions
    conv_half<<<(NTOK * EDIM / 4 + 255) / 256, 256>>>(x, xf, NTOK * EDIM / 4);
    conv_half<<<(QCOLS * EDIM / 4 + 255) / 256, 256>>>(Wq, wq, QCOLS * EDIM / 4);
    conv_half<<<(EDIM * EDIM / 4 + 255) / 256, 256>>>(Wk, wk, EDIM * EDIM / 4);
    conv_half<<<(EDIM * EDIM / 4 + 255) / 256, 256>>>(Wv, wv, EDIM * EDIM / 4);
    conv_half<<<(EDIM * EDIM / 4 + 255) / 256, 256>>>(Wo, wo, EDIM * EDIM / 4);

    // 2) projections (tensor cores, fp16)
    gemm_f16<__half><<<dim3(QCOLS / 128, NTOK / 128), 256, GSMEM>>>(xf, wq, bq, gq, QCOLS, EDIM);
    gemm_f16<__half><<<dim3(EDIM / 128,  NTOK / 128), 256, GSMEM>>>(xf, wk, bk, gk, EDIM, EDIM);
    gemm_f16<__half><<<dim3(EDIM / 128,  NTOK / 128), 256, GSMEM>>>(xf, wv, bv, gv, EDIM, EDIM);

    // 3) per-token attention -> y fp16 ((B,H,S,D) flat == (B,S,E) flat)
    attn_kernel<<<NTOK, 256>>>(gq, gk, gv, gy);

    // 4) output projection (fp32 out)
    gemm_f16<float><<<dim3(EDIM / 128, NTOK / 128), 256, GSMEM>>>(gy, wo, bo, out, EDIM, EDIM);
}

// round 6
// speedup vs baseline: 6.0639x; 1.1086x over previous
#include <cuda_runtime.h>
#include <cuda_fp16.h>
#include <cstdint>

#define BATCH 4
#define SEQ   2048
#define EDIM  1024
#define QN    4
#define HN    16
#define DH    64
#define NTOK  (BATCH*SEQ)        // 8192
#define QCOLS (QN*EDIM)          // 4096
#define NQKV  (QCOLS + 2*EDIM)   // 6144

// ------------------------- scratch (static, no runtime alloc) ---------------
__device__ __half g_qkv[(size_t)NTOK * NQKV];    // fused q|k|v projections
__device__ __half g_xf[(size_t)NTOK * EDIM];     // x fp16
__device__ __half g_y[(size_t)NTOK * EDIM];      // attn out (B,H,S,D) flat
__device__ __half g_wqkv[(size_t)NQKV * EDIM];   // packed Wq|Wk|Wv fp16
__device__ __half g_wo[(size_t)EDIM * EDIM];

// ------------------------- helpers ------------------------------------------
__device__ __forceinline__ uint32_t smem_to_u32(const void* p) {
    uint32_t a;
    asm("{ .reg .u64 t; cvta.to.shared.u64 t, %1; cvt.u32.u64 %0, t; }" : "=r"(a) : "l"(p));
    return a;
}
__device__ __forceinline__ void cp16(uint32_t dst, const void* src) {
    asm volatile("cp.async.cg.shared.global [%0], [%1], 16;" :: "r"(dst), "l"(src));
}
__device__ __forceinline__ void cp_commit() { asm volatile("cp.async.commit_group;" ::: "memory"); }
__device__ __forceinline__ void cp_wait0()  { asm volatile("cp.async.wait_group 0;"  ::: "memory"); }
__device__ __forceinline__ void cp_wait1()  { asm volatile("cp.async.wait_group 1;"  ::: "memory"); }
__device__ __forceinline__ void ldx4(uint32_t* r, uint32_t addr) {
    asm volatile("ldmatrix.sync.aligned.m8n8.x4.shared.b16 {%0,%1,%2,%3}, [%4];"
        : "=r"(r[0]), "=r"(r[1]), "=r"(r[2]), "=r"(r[3]) : "r"(addr));
}
__device__ __forceinline__ void mma16816(float* d, const uint32_t* a, const uint32_t* b) {
    asm volatile("mma.sync.aligned.m16n8k16.row.col.f32.f16.f16.f32 "
        "{%0,%1,%2,%3}, {%4,%5,%6,%7}, {%8,%9}, {%0,%1,%2,%3};"
        : "+f"(d[0]), "+f"(d[1]), "+f"(d[2]), "+f"(d[3])
        : "r"(a[0]), "r"(a[1]), "r"(a[2]), "r"(a[3]), "r"(b[0]), "r"(b[1]));
}

// ------------------------- fused conversion ---------------------------------
// Segments (float4 units): x | Wq | Wk | Wv | Wo
#define S_X   2097152                      // 8192*1024/4
#define S_WQ  (S_X  + 1048576)             // +4096*1024/4
#define S_WK  (S_WQ + 262144)
#define S_WV  (S_WK + 262144)
#define S_ALL (S_WV + 262144)

__device__ __forceinline__ uint2 f4_to_h4(float4 v) {
    __half2 h[2];
    h[0] = __floats2half2_rn(v.x, v.y);
    h[1] = __floats2half2_rn(v.z, v.w);
    return *(uint2*)h;
}

__global__ void __launch_bounds__(256)
conv_all(const float* __restrict__ x, const float* __restrict__ Wq,
         const float* __restrict__ Wk, const float* __restrict__ Wv,
         const float* __restrict__ Wo, __half* __restrict__ xf,
         __half* __restrict__ wqkv, __half* __restrict__ wo)
{
    int i = blockIdx.x * 256 + threadIdx.x;
    if (i >= S_ALL) return;
    const float4* src; uint2* dst; int j;
    if (i < S_X)       { src = (const float4*)x;  dst = (uint2*)xf;   j = i; }
    else if (i < S_WQ) { src = (const float4*)Wq; dst = (uint2*)wqkv; j = i - S_X;
                         dst += 0;        }
    else if (i < S_WK) { src = (const float4*)Wk; dst = (uint2*)wqkv + 1048576; j = i - S_WQ; }
    else if (i < S_WV) { src = (const float4*)Wv; dst = (uint2*)wqkv + 1310720; j = i - S_WK; }
    else               { src = (const float4*)Wo; dst = (uint2*)wo;   j = i - S_WV; }
    dst[j] = f4_to_h4(src[j]);
}

// ------------------------- HMMA fp16 GEMM -----------------------------------
// C[m,n] = sum_k A[m,k]*W[n,k] + bias[n].  128x128 CTA tile, BK=32,
// 4 warps (warp tile 64x64), 3-stage cp.async pipeline.
#define GBK    32
#define ROWB   80                  // 64B data + 16B pad (conflict-free ldmatrix)
#define TILEB  (128 * ROWB)        // 10240 B
#define STAGEB (2 * TILEB)         // A, W
#define NSTG   3
#define GSMEM  (NSTG * STAGEB)     // 61440 B

template <typename OutT>
__global__ void __launch_bounds__(128, 2)
gemm_f16(const __half* __restrict__ A, const __half* __restrict__ W,
         const float* __restrict__ bias0, const float* __restrict__ bias1,
         const float* __restrict__ bias2, int nb1, int nb2,
         OutT* __restrict__ C, int N, int K)
{
    extern __shared__ __align__(16) char smem[];
    const uint32_t sb = smem_to_u32(smem);
    const int tid = threadIdx.x;
    const int lane = tid & 31;
    const int warp = tid >> 5;
    const int bm = blockIdx.y * 128;
    const int bn = blockIdx.x * 128;
    const int wm0 = (warp & 1) * 64;
    const int wn0 = (warp >> 1) * 64;

    float acc[4][8][4];
#pragma unroll
    for (int i = 0; i < 4; i++)
#pragma unroll
        for (int j = 0; j < 8; j++)
#pragma unroll
            for (int r = 0; r < 4; r++) acc[i][j][r] = 0.f;

    const int lrow = tid >> 2;     // 0..31
    const int lq   = tid & 3;

    auto load_chunk = [&](int stage, int ck) {
        const uint32_t stb = sb + stage * STAGEB;
#pragma unroll
        for (int l = 0; l < 4; l++) {
            int row = lrow + l * 32;
            uint32_t dst = stb + row * ROWB + lq * 16;
            cp16(dst, A + (size_t)(bm + row) * K + ck * GBK + lq * 8);
            cp16(dst + TILEB, W + (size_t)(bn + row) * K + ck * GBK + lq * 8);
        }
    };

    auto compute = [&](int stage) {
        const uint32_t tA = sb + stage * STAGEB;
        const uint32_t tW = tA + TILEB;
#pragma unroll
        for (int ks = 0; ks < 2; ks++) {
            uint32_t a[4][4], b[4][4];
            const uint32_t kb = ks * 32;
#pragma unroll
            for (int rb = 0; rb < 4; rb++) {
                uint32_t off = (uint32_t)(wm0 + rb * 16 + (lane & 15)) * ROWB
                             + kb + ((lane >> 4) << 4);
                ldx4(a[rb], tA + off);
            }
#pragma unroll
            for (int hb = 0; hb < 4; hb++) {
                uint32_t off = (uint32_t)(wn0 + hb * 16 + (lane & 7) + ((lane >> 4) << 3)) * ROWB
                             + kb + (((lane >> 3) & 1) << 4);
                ldx4(b[hb], tW + off);
            }
#pragma unroll
            for (int rb = 0; rb < 4; rb++) {
#pragma unroll
                for (int nb = 0; nb < 8; nb++) {
                    mma16816(acc[rb][nb], a[rb], &b[nb >> 1][(nb & 1) * 2]);
                }
            }
        }
    };

    const int nchunk = K / GBK;
    load_chunk(0, 0); cp_commit();
    load_chunk(1, 1); cp_commit();
    for (int c = 0; c < nchunk; c++) {
        if (c == nchunk - 1) cp_wait0(); else cp_wait1();
        __syncthreads();
        if (c + 2 < nchunk) { load_chunk((c + 2) % NSTG, c + 2); cp_commit(); }
        compute(c % NSTG);
    }

    // bias segment select (bn is segment-uniform: boundaries are multiples of 128)
    const float* bp; int segbase;
    if (bn < nb1)      { bp = bias0; segbase = 0;   }
    else if (bn < nb2) { bp = bias1; segbase = nb1; }
    else               { bp = bias2; segbase = nb2; }

    // epilogue
#pragma unroll
    for (int rb = 0; rb < 4; rb++) {
#pragma unroll
        for (int nb = 0; nb < 8; nb++) {
            int row = bm + wm0 + rb * 16 + (lane >> 2);
            int col = bn + wn0 + nb * 8 + (lane & 3) * 2;
            float b0 = bp[col - segbase], b1 = bp[col - segbase + 1];
            float o0 = acc[rb][nb][0] + b0, o1 = acc[rb][nb][1] + b1;
            float o2 = acc[rb][nb][2] + b0, o3 = acc[rb][nb][3] + b1;
            if constexpr (sizeof(OutT) == 2) {
                __half2 h0 = __floats2half2_rn(o0, o1);
                __half2 h1 = __floats2half2_rn(o2, o3);
                *(__half2*)((__half*)C + (size_t)row * N + col)       = h0;
                *(__half2*)((__half*)C + (size_t)(row + 8) * N + col) = h1;
            } else {
                float2 v0 = {o0, o1}, v1 = {o2, o3};
                *(float2*)((float*)C + (size_t)row * N + col)       = v0;
                *(float2*)((float*)C + (size_t)(row + 8) * N + col) = v1;
            }
        }
    }
}

// ------------------------- per-token head-mixing attention ------------------
// qkv row layout: [q(4096) | k(1024) | v(1024)] per token (stride NQKV).
__global__ void __launch_bounds__(256)
attn_kernel(const __half* __restrict__ gqkv, __half* __restrict__ gy)
{
    const int tok = blockIdx.x;
    const int t = threadIdx.x;
    const __half* base = gqkv + (size_t)tok * NQKV;

    __shared__ __align__(16) float qs[QN * HN * DH];
    __shared__ float ks[HN][DH + 1];
    __shared__ __align__(16) float vs[HN][DH];
    __shared__ float sc[QN][HN][HN];
    __shared__ float ps[HN][HN];

    // load q (fp16 -> fp32 smem)
    {
        const uint4* qg = (const uint4*)base;
#pragma unroll
        for (int l = 0; l < 2; l++) {
            uint4 p = qg[t + l * 256];
            const __half2* hp = (const __half2*)&p;
            float* dst = qs + (t + l * 256) * 8;
#pragma unroll
            for (int j = 0; j < 4; j++) {
                float2 f = __half22float2(hp[j]);
                dst[2 * j] = f.x; dst[2 * j + 1] = f.y;
            }
        }
    }
    // load k (threads 0..127) and v (threads 128..255)
    if (t < 128) {
        uint4 p = ((const uint4*)(base + QCOLS))[t];
        const __half2* hp = (const __half2*)&p;
        int g = t >> 3, d = (t * 8) & 63;
#pragma unroll
        for (int j = 0; j < 4; j++) {
            float2 f = __half22float2(hp[j]);
            ks[g][d + 2 * j] = f.x; ks[g][d + 2 * j + 1] = f.y;
        }
    } else {
        int tt = t - 128;
        uint4 p = ((const uint4*)(base + QCOLS + EDIM))[tt];
        const __half2* hp = (const __half2*)&p;
        int g = tt >> 3, d = (tt * 8) & 63;
#pragma unroll
        for (int j = 0; j < 4; j++) {
            float2 f = __half22float2(hp[j]);
            vs[g][d + 2 * j] = f.x; vs[g][d + 2 * j + 1] = f.y;
        }
    }
    __syncthreads();

    const float scale = 0.125f;
#pragma unroll
    for (int l = 0; l < 4; l++) {
        int e = t + l * 256;
        int qq = e >> 8, h = (e >> 4) & 15, g = e & 15;
        const float* qp = qs + (qq * HN + h) * DH;
        const float* kp = ks[g];
        float s_ = 0.f;
#pragma unroll
        for (int d = 0; d < DH; d++) s_ = fmaf(qp[d], kp[d], s_);
        sc[qq][h][g] = s_ * scale;
    }
    __syncthreads();

    if (t < 64) {
        int qq = t >> 4, h = t & 15;
        float* row = sc[qq][h];
        float m = row[0];
#pragma unroll
        for (int g = 1; g < 16; g++) m = fmaxf(m, row[g]);
        float ssum = 0.f;
#pragma unroll
        for (int g = 0; g < 16; g++) { float ex = __expf(row[g] - m); row[g] = ex; ssum += ex; }
        float inv = 1.f / ssum;
#pragma unroll
        for (int g = 0; g < 16; g++) row[g] *= inv;
    }
    __syncthreads();

    {
        int h = t >> 4, g = t & 15;
        ps[h][g] = sc[0][h][g] + sc[1][h][g] + sc[2][h][g] + sc[3][h][g];
    }
    __syncthreads();

    const int b = tok >> 11, s = tok & 2047;
    {
        int h = t >> 4;
        int d0 = (t * 4) & 63;
        float o[4];
#pragma unroll
        for (int j = 0; j < 4; j++) o[j] = 0.f;
#pragma unroll
        for (int g = 0; g < 16; g++) {
            float p = ps[h][g];
#pragma unroll
            for (int j = 0; j < 4; j++) o[j] = fmaf(p, vs[g][d0 + j], o[j]);
        }
        __half2 h0 = __floats2half2_rn(o[0], o[1]);
        __half2 h1 = __floats2half2_rn(o[2], o[3]);
        size_t oi = (((size_t)b * HN + h) * SEQ + s) * DH + d0;
        *(__half2*)(gy + oi)     = h0;
        *(__half2*)(gy + oi + 2) = h1;
    }
}

// ------------------------- launch -------------------------------------------
extern "C" void kernel_launch(void* const* d_in, const int* in_sizes, int n_in,
                              void* d_out, int out_size)
{
    const float* x  = (const float*)d_in[0];
    const float* Wq = (const float*)d_in[1];
    const float* bq = (const float*)d_in[2];
    const float* Wk = (const float*)d_in[3];
    const float* bk = (const float*)d_in[4];
    const float* Wv = (const float*)d_in[5];
    const float* bv = (const float*)d_in[6];
    const float* Wo = (const float*)d_in[7];
    const float* bo = (const float*)d_in[8];
    float* out = (float*)d_out;
    (void)in_sizes; (void)n_in; (void)out_size;

    __half *qkv, *xf, *gy, *wqkv, *wo;
    cudaGetSymbolAddress((void**)&qkv, g_qkv);
    cudaGetSymbolAddress((void**)&xf, g_xf);
    cudaGetSymbolAddress((void**)&gy, g_y);
    cudaGetSymbolAddress((void**)&wqkv, g_wqkv);
    cudaGetSymbolAddress((void**)&wo, g_wo);

    cudaFuncSetAttribute(gemm_f16<float>,  cudaFuncAttributeMaxDynamicSharedMemorySize, GSMEM);
    cudaFuncSetAttribute(gemm_f16<__half>, cudaFuncAttributeMaxDynamicSharedMemorySize, GSMEM);

    // 1) fused fp32 -> fp16 conversions (x + packed QKV weights + Wo)
    conv_all<<<(S_ALL + 255) / 256, 256>>>(x, Wq, Wk, Wv, Wo, xf, wqkv, wo);

    // 2) fused QKV projection (N = 6144), bias segment-selected per CTA
    gemm_f16<__half><<<dim3(NQKV / 128, NTOK / 128), 128, GSMEM>>>(
        xf, wqkv, bq, bk, bv, QCOLS, QCOLS + EDIM, qkv, NQKV, EDIM);

    // 3) per-token attention -> y fp16 ((B,H,S,D) flat == (B,S,E) flat)
    attn_kernel<<<NTOK, 256>>>(qkv, gy);

    // 4) output projection (fp32 out)
    gemm_f16<float><<<dim3(EDIM / 128, NTOK / 128), 128, GSMEM>>>(
        gy, wo, bo, bo, bo, 1 << 30, 1 << 30, out, EDIM, EDIM);
}

// round 7
// speedup vs baseline: 6.8622x; 1.1316x over previous
#include <cuda_runtime.h>
#include <cuda_fp16.h>
#include <cstdint>

#define BATCH 4
#define SEQ   2048
#define EDIM  1024
#define QN    4
#define HN    16
#define DH    64
#define NTOK  (BATCH*SEQ)        // 8192
#define QCOLS (QN*EDIM)          // 4096
#define NQKV  (QCOLS + 2*EDIM)   // 6144

// ------------------------- scratch (static, no runtime alloc) ---------------
__device__ __half g_qkv[(size_t)NTOK * NQKV];    // fused q|k|v projections
__device__ __half g_xf[(size_t)NTOK * EDIM];     // x fp16
__device__ __half g_y[(size_t)NTOK * EDIM];      // attn out (B,H,S,D) flat
__device__ __half g_wqkv[(size_t)NQKV * EDIM];   // packed Wq|Wk|Wv fp16
__device__ __half g_wo[(size_t)EDIM * EDIM];

// ------------------------- helpers ------------------------------------------
__device__ __forceinline__ uint32_t smem_to_u32(const void* p) {
    uint32_t a;
    asm("{ .reg .u64 t; cvta.to.shared.u64 t, %1; cvt.u32.u64 %0, t; }" : "=r"(a) : "l"(p));
    return a;
}
__device__ __forceinline__ void cp16(uint32_t dst, const void* src) {
    asm volatile("cp.async.cg.shared.global [%0], [%1], 16;" :: "r"(dst), "l"(src));
}
__device__ __forceinline__ void cp_commit() { asm volatile("cp.async.commit_group;" ::: "memory"); }
__device__ __forceinline__ void cp_wait0()  { asm volatile("cp.async.wait_group 0;"  ::: "memory"); }
__device__ __forceinline__ void ldx4(uint32_t* r, uint32_t addr) {
    asm volatile("ldmatrix.sync.aligned.m8n8.x4.shared.b16 {%0,%1,%2,%3}, [%4];"
        : "=r"(r[0]), "=r"(r[1]), "=r"(r[2]), "=r"(r[3]) : "r"(addr));
}
__device__ __forceinline__ void mma16816(float* d, const uint32_t* a, const uint32_t* b) {
    asm volatile("mma.sync.aligned.m16n8k16.row.col.f32.f16.f16.f32 "
        "{%0,%1,%2,%3}, {%4,%5,%6,%7}, {%8,%9}, {%0,%1,%2,%3};"
        : "+f"(d[0]), "+f"(d[1]), "+f"(d[2]), "+f"(d[3])
        : "r"(a[0]), "r"(a[1]), "r"(a[2]), "r"(a[3]), "r"(b[0]), "r"(b[1]));
}

// ------------------------- fused conversion ---------------------------------
// Segments (float4 units): x | Wq | Wk | Wv | Wo
#define S_X   2097152                      // 8192*1024/4
#define S_WQ  (S_X  + 1048576)             // +4096*1024/4
#define S_WK  (S_WQ + 262144)
#define S_WV  (S_WK + 262144)
#define S_ALL (S_WV + 262144)

__device__ __forceinline__ uint2 f4_to_h4(float4 v) {
    __half2 h[2];
    h[0] = __floats2half2_rn(v.x, v.y);
    h[1] = __floats2half2_rn(v.z, v.w);
    return *(uint2*)h;
}

__global__ void __launch_bounds__(256)
conv_all(const float* __restrict__ x, const float* __restrict__ Wq,
         const float* __restrict__ Wk, const float* __restrict__ Wv,
         const float* __restrict__ Wo, __half* __restrict__ xf,
         __half* __restrict__ wqkv, __half* __restrict__ wo)
{
    int i = blockIdx.x * 256 + threadIdx.x;
    if (i >= S_ALL) return;
    const float4* src; uint2* dst; int j;
    if (i < S_X)       { src = (const float4*)x;  dst = (uint2*)xf;   j = i; }
    else if (i < S_WQ) { src = (const float4*)Wq; dst = (uint2*)wqkv; j = i - S_X; }
    else if (i < S_WK) { src = (const float4*)Wk; dst = (uint2*)wqkv + 1048576; j = i - S_WQ; }
    else if (i < S_WV) { src = (const float4*)Wv; dst = (uint2*)wqkv + 1310720; j = i - S_WK; }
    else               { src = (const float4*)Wo; dst = (uint2*)wo;   j = i - S_WV; }
    dst[j] = f4_to_h4(src[j]);
}

// ------------------------- HMMA fp16 GEMM -----------------------------------
// C[m,n] = sum_k A[m,k]*W[n,k] + bias[n].  128x128 CTA tile, BK=64,
// 4 warps (warp tile 64x64), 2-stage cp.async, XOR-swizzled 128B rows:
// quarter (16B unit) q of row r stored at q ^ (r & 7) -> conflict-free
// for both cp.async stores and ldmatrix reads.
#define GBK    64
#define TILEB  (128 * 128)          // 16384 B
#define STAGEB (2 * TILEB)          // A, W = 32768 B
#define NSTG   2
#define GSMEM  (NSTG * STAGEB)      // 65536 B

template <typename OutT>
__global__ void __launch_bounds__(128, 2)
gemm_f16(const __half* __restrict__ A, const __half* __restrict__ W,
         const float* __restrict__ bias0, const float* __restrict__ bias1,
         const float* __restrict__ bias2, int nb1, int nb2,
         OutT* __restrict__ C, int N, int K)
{
    extern __shared__ __align__(16) char smem[];
    const uint32_t sb = smem_to_u32(smem);
    const int tid = threadIdx.x;
    const int lane = tid & 31;
    const int warp = tid >> 5;
    const int bm = blockIdx.y * 128;
    const int bn = blockIdx.x * 128;
    const int wm0 = (warp & 1) * 64;
    const int wn0 = (warp >> 1) * 64;

    float acc[4][8][4];
#pragma unroll
    for (int i = 0; i < 4; i++)
#pragma unroll
        for (int j = 0; j < 8; j++)
#pragma unroll
            for (int r = 0; r < 4; r++) acc[i][j][r] = 0.f;

    const int lrow = tid >> 3;     // 0..15
    const int lq   = tid & 7;      // quarter 0..7 within 128B row

    auto load_chunk = [&](int stage, int ck) {
        const uint32_t stb = sb + stage * STAGEB;
#pragma unroll
        for (int l = 0; l < 8; l++) {
            int row = lrow + l * 16;
            uint32_t dst = stb + row * 128 + ((lq ^ (row & 7)) << 4);
            const size_t kof = (size_t)ck * GBK + lq * 8;
            cp16(dst,         A + (size_t)(bm + row) * K + kof);
            cp16(dst + TILEB, W + (size_t)(bn + row) * K + kof);
        }
    };

    // precomputed per-thread frag rows
    const int arow[4] = {wm0 + 0 * 16 + (lane & 15), wm0 + 1 * 16 + (lane & 15),
                         wm0 + 2 * 16 + (lane & 15), wm0 + 3 * 16 + (lane & 15)};
    const int ahalf = lane >> 4;                       // 0/1
    const int brow[4] = {wn0 + 0 * 16 + (lane & 7) + ((lane >> 4) << 3),
                         wn0 + 1 * 16 + (lane & 7) + ((lane >> 4) << 3),
                         wn0 + 2 * 16 + (lane & 7) + ((lane >> 4) << 3),
                         wn0 + 3 * 16 + (lane & 7) + ((lane >> 4) << 3)};
    const int bhalf = (lane >> 3) & 1;

    auto compute = [&](int stage) {
        const uint32_t tA = sb + stage * STAGEB;
        const uint32_t tW = tA + TILEB;
#pragma unroll
        for (int ks = 0; ks < 4; ks++) {
            uint32_t a[4][4], b[4][4];
#pragma unroll
            for (int rb = 0; rb < 4; rb++) {
                int r = arow[rb];
                uint32_t q = (uint32_t)((2 * ks + ahalf) ^ (r & 7));
                ldx4(a[rb], tA + (uint32_t)r * 128 + (q << 4));
            }
#pragma unroll
            for (int hb = 0; hb < 4; hb++) {
                int r = brow[hb];
                uint32_t q = (uint32_t)((2 * ks + bhalf) ^ (r & 7));
                ldx4(b[hb], tW + (uint32_t)r * 128 + (q << 4));
            }
#pragma unroll
            for (int rb = 0; rb < 4; rb++) {
#pragma unroll
                for (int nb = 0; nb < 8; nb++) {
                    mma16816(acc[rb][nb], a[rb], &b[nb >> 1][(nb & 1) * 2]);
                }
            }
        }
    };

    const int nchunk = K / GBK;   // 16
    load_chunk(0, 0); cp_commit();
    for (int c = 0; c < nchunk; c++) {
        cp_wait0();
        __syncthreads();
        if (c + 1 < nchunk) { load_chunk((c + 1) & 1, c + 1); cp_commit(); }
        compute(c & 1);
    }

    // bias segment select (bn is segment-uniform: boundaries are multiples of 128)
    const float* bp; int segbase;
    if (bn < nb1)      { bp = bias0; segbase = 0;   }
    else if (bn < nb2) { bp = bias1; segbase = nb1; }
    else               { bp = bias2; segbase = nb2; }

    // epilogue
#pragma unroll
    for (int rb = 0; rb < 4; rb++) {
#pragma unroll
        for (int nb = 0; nb < 8; nb++) {
            int row = bm + wm0 + rb * 16 + (lane >> 2);
            int col = bn + wn0 + nb * 8 + (lane & 3) * 2;
            float b0 = bp[col - segbase], b1 = bp[col - segbase + 1];
            float o0 = acc[rb][nb][0] + b0, o1 = acc[rb][nb][1] + b1;
            float o2 = acc[rb][nb][2] + b0, o3 = acc[rb][nb][3] + b1;
            if constexpr (sizeof(OutT) == 2) {
                __half2 h0 = __floats2half2_rn(o0, o1);
                __half2 h1 = __floats2half2_rn(o2, o3);
                *(__half2*)((__half*)C + (size_t)row * N + col)       = h0;
                *(__half2*)((__half*)C + (size_t)(row + 8) * N + col) = h1;
            } else {
                float2 v0 = {o0, o1}, v1 = {o2, o3};
                *(float2*)((float*)C + (size_t)row * N + col)       = v0;
                *(float2*)((float*)C + (size_t)(row + 8) * N + col) = v1;
            }
        }
    }
}

// ------------------------- per-token head-mixing attention ------------------
// qkv row layout: [q(4096) | k(1024) | v(1024)] per token (stride NQKV).
__global__ void __launch_bounds__(256)
attn_kernel(const __half* __restrict__ gqkv, __half* __restrict__ gy)
{
    const int tok = blockIdx.x;
    const int t = threadIdx.x;
    const __half* base = gqkv + (size_t)tok * NQKV;

    __shared__ __align__(16) float qs[QN * HN * DH];
    __shared__ float ks[HN][DH + 1];
    __shared__ __align__(16) float vs[HN][DH];
    __shared__ float sc[QN][HN][HN];
    __shared__ float ps[HN][HN];

    {
        const uint4* qg = (const uint4*)base;
#pragma unroll
        for (int l = 0; l < 2; l++) {
            uint4 p = qg[t + l * 256];
            const __half2* hp = (const __half2*)&p;
            float* dst = qs + (t + l * 256) * 8;
#pragma unroll
            for (int j = 0; j < 4; j++) {
                float2 f = __half22float2(hp[j]);
                dst[2 * j] = f.x; dst[2 * j + 1] = f.y;
            }
        }
    }
    if (t < 128) {
        uint4 p = ((const uint4*)(base + QCOLS))[t];
        const __half2* hp = (const __half2*)&p;
        int g = t >> 3, d = (t * 8) & 63;
#pragma unroll
        for (int j = 0; j < 4; j++) {
            float2 f = __half22float2(hp[j]);
            ks[g][d + 2 * j] = f.x; ks[g][d + 2 * j + 1] = f.y;
        }
    } else {
        int tt = t - 128;
        uint4 p = ((const uint4*)(base + QCOLS + EDIM))[tt];
        const __half2* hp = (const __half2*)&p;
        int g = tt >> 3, d = (tt * 8) & 63;
#pragma unroll
        for (int j = 0; j < 4; j++) {
            float2 f = __half22float2(hp[j]);
            vs[g][d + 2 * j] = f.x; vs[g][d + 2 * j + 1] = f.y;
        }
    }
    __syncthreads();

    const float scale = 0.125f;
#pragma unroll
    for (int l = 0; l < 4; l++) {
        int e = t + l * 256;
        int qq = e >> 8, h = (e >> 4) & 15, g = e & 15;
        const float* qp = qs + (qq * HN + h) * DH;
        const float* kp = ks[g];
        float s_ = 0.f;
#pragma unroll
        for (int d = 0; d < DH; d++) s_ = fmaf(qp[d], kp[d], s_);
        sc[qq][h][g] = s_ * scale;
    }
    __syncthreads();

    if (t < 64) {
        int qq = t >> 4, h = t & 15;
        float* row = sc[qq][h];
        float m = row[0];
#pragma unroll
        for (int g = 1; g < 16; g++) m = fmaxf(m, row[g]);
        float ssum = 0.f;
#pragma unroll
        for (int g = 0; g < 16; g++) { float ex = __expf(row[g] - m); row[g] = ex; ssum += ex; }
        float inv = 1.f / ssum;
#pragma unroll
        for (int g = 0; g < 16; g++) row[g] *= inv;
    }
    __syncthreads();

    {
        int h = t >> 4, g = t & 15;
        ps[h][g] = sc[0][h][g] + sc[1][h][g] + sc[2][h][g] + sc[3][h][g];
    }
    __syncthreads();

    const int b = tok >> 11, s = tok & 2047;
    {
        int h = t >> 4;
        int d0 = (t * 4) & 63;
        float o[4];
#pragma unroll
        for (int j = 0; j < 4; j++) o[j] = 0.f;
#pragma unroll
        for (int g = 0; g < 16; g++) {
            float p = ps[h][g];
#pragma unroll
            for (int j = 0; j < 4; j++) o[j] = fmaf(p, vs[g][d0 + j], o[j]);
        }
        __half2 h0 = __floats2half2_rn(o[0], o[1]);
        __half2 h1 = __floats2half2_rn(o[2], o[3]);
        size_t oi = (((size_t)b * HN + h) * SEQ + s) * DH + d0;
        *(__half2*)(gy + oi)     = h0;
        *(__half2*)(gy + oi + 2) = h1;
    }
}

// ------------------------- launch -------------------------------------------
extern "C" void kernel_launch(void* const* d_in, const int* in_sizes, int n_in,
                              void* d_out, int out_size)
{
    const float* x  = (const float*)d_in[0];
    const float* Wq = (const float*)d_in[1];
    const float* bq = (const float*)d_in[2];
    const float* Wk = (const float*)d_in[3];
    const float* bk = (const float*)d_in[4];
    const float* Wv = (const float*)d_in[5];
    const float* bv = (const float*)d_in[6];
    const float* Wo = (const float*)d_in[7];
    const float* bo = (const float*)d_in[8];
    float* out = (float*)d_out;
    (void)in_sizes; (void)n_in; (void)out_size;

    __half *qkv, *xf, *gy, *wqkv, *wo;
    cudaGetSymbolAddress((void**)&qkv, g_qkv);
    cudaGetSymbolAddress((void**)&xf, g_xf);
    cudaGetSymbolAddress((void**)&gy, g_y);
    cudaGetSymbolAddress((void**)&wqkv, g_wqkv);
    cudaGetSymbolAddress((void**)&wo, g_wo);

    cudaFuncSetAttribute(gemm_f16<float>,  cudaFuncAttributeMaxDynamicSharedMemorySize, GSMEM);
    cudaFuncSetAttribute(gemm_f16<__half>, cudaFuncAttributeMaxDynamicSharedMemorySize, GSMEM);

    // 1) fused fp32 -> fp16 conversions (x + packed QKV weights + Wo)
    conv_all<<<(S_ALL + 255) / 256, 256>>>(x, Wq, Wk, Wv, Wo, xf, wqkv, wo);

    // 2) fused QKV projection (N = 6144), bias segment-selected per CTA
    gemm_f16<__half><<<dim3(NQKV / 128, NTOK / 128), 128, GSMEM>>>(
        xf, wqkv, bq, bk, bv, QCOLS, QCOLS + EDIM, qkv, NQKV, EDIM);

    // 3) per-token attention -> y fp16 ((B,H,S,D) flat == (B,S,E) flat)
    attn_kernel<<<NTOK, 256>>>(qkv, gy);

    // 4) output projection (fp32 out)
    gemm_f16<float><<<dim3(EDIM / 128, NTOK / 128), 128, GSMEM>>>(
        gy, wo, bo, bo, bo, 1 << 30, 1 << 30, out, EDIM, EDIM);
}

// round 8
// speedup vs baseline: 7.0930x; 1.0336x over previous
#include <cuda_runtime.h>
#include <cuda_fp16.h>
#include <cstdint>

#define BATCH 4
#define SEQ   2048
#define EDIM  1024
#define QN    4
#define HN    16
#define DH    64
#define NTOK  (BATCH*SEQ)        // 8192
#define QCOLS (QN*EDIM)          // 4096
#define NQKV  (QCOLS + 2*EDIM)   // 6144

// ------------------------- scratch (static, no runtime alloc) ---------------
__device__ __half g_qkv[(size_t)NTOK * NQKV];    // fused q|k|v projections
__device__ __half g_xf[(size_t)NTOK * EDIM];     // x fp16
__device__ __half g_y[(size_t)NTOK * EDIM];      // attn out (B,H,S,D) flat
__device__ __half g_wqkv[(size_t)NQKV * EDIM];   // packed Wq|Wk|Wv fp16
__device__ __half g_wo[(size_t)EDIM * EDIM];

// ------------------------- helpers ------------------------------------------
__device__ __forceinline__ uint32_t smem_to_u32(const void* p) {
    uint32_t a;
    asm("{ .reg .u64 t; cvta.to.shared.u64 t, %1; cvt.u32.u64 %0, t; }" : "=r"(a) : "l"(p));
    return a;
}
__device__ __forceinline__ void cp16(uint32_t dst, const void* src) {
    asm volatile("cp.async.cg.shared.global [%0], [%1], 16;" :: "r"(dst), "l"(src));
}
__device__ __forceinline__ void cp_commit() { asm volatile("cp.async.commit_group;" ::: "memory"); }
__device__ __forceinline__ void cp_wait0()  { asm volatile("cp.async.wait_group 0;"  ::: "memory"); }
__device__ __forceinline__ void cp_wait1()  { asm volatile("cp.async.wait_group 1;"  ::: "memory"); }
__device__ __forceinline__ void ldx4(uint32_t* r, uint32_t addr) {
    asm volatile("ldmatrix.sync.aligned.m8n8.x4.shared.b16 {%0,%1,%2,%3}, [%4];"
        : "=r"(r[0]), "=r"(r[1]), "=r"(r[2]), "=r"(r[3]) : "r"(addr));
}
__device__ __forceinline__ void mma16816(float* d, const uint32_t* a, const uint32_t* b) {
    asm volatile("mma.sync.aligned.m16n8k16.row.col.f32.f16.f16.f32 "
        "{%0,%1,%2,%3}, {%4,%5,%6,%7}, {%8,%9}, {%0,%1,%2,%3};"
        : "+f"(d[0]), "+f"(d[1]), "+f"(d[2]), "+f"(d[3])
        : "r"(a[0]), "r"(a[1]), "r"(a[2]), "r"(a[3]), "r"(b[0]), "r"(b[1]));
}

// ------------------------- fused conversion ---------------------------------
// Segments (float4 units): x | Wq | Wk | Wv | Wo
#define S_X   2097152                      // 8192*1024/4
#define S_WQ  (S_X  + 1048576)             // +4096*1024/4
#define S_WK  (S_WQ + 262144)
#define S_WV  (S_WK + 262144)
#define S_ALL (S_WV + 262144)

__device__ __forceinline__ uint2 f4_to_h4(float4 v) {
    __half2 h[2];
    h[0] = __floats2half2_rn(v.x, v.y);
    h[1] = __floats2half2_rn(v.z, v.w);
    return *(uint2*)h;
}

__global__ void __launch_bounds__(256)
conv_all(const float* __restrict__ x, const float* __restrict__ Wq,
         const float* __restrict__ Wk, const float* __restrict__ Wv,
         const float* __restrict__ Wo, __half* __restrict__ xf,
         __half* __restrict__ wqkv, __half* __restrict__ wo)
{
    int i = blockIdx.x * 256 + threadIdx.x;
    if (i >= S_ALL) return;
    const float4* src; uint2* dst; int j;
    if (i < S_X)       { src = (const float4*)x;  dst = (uint2*)xf;   j = i; }
    else if (i < S_WQ) { src = (const float4*)Wq; dst = (uint2*)wqkv; j = i - S_X; }
    else if (i < S_WK) { src = (const float4*)Wk; dst = (uint2*)wqkv + 1048576; j = i - S_WQ; }
    else if (i < S_WV) { src = (const float4*)Wv; dst = (uint2*)wqkv + 1310720; j = i - S_WK; }
    else               { src = (const float4*)Wo; dst = (uint2*)wo;   j = i - S_WV; }
    dst[j] = f4_to_h4(src[j]);
}

// ------------------------- HMMA fp16 GEMM -----------------------------------
// C[m,n] = sum_k A[m,k]*W[n,k] + bias[n].  128x128 CTA tile, BK=64,
// 4 warps (warp tile 64x64), 3-stage cp.async (2 chunks in flight),
// XOR-swizzled 128B rows: quarter q of row r stored at q ^ (r & 7).
#define GBK    64
#define TILEB  (128 * 128)          // 16384 B
#define STAGEB (2 * TILEB)          // A, W = 32768 B
#define NSTG   3
#define GSMEM  (NSTG * STAGEB)      // 98304 B

template <typename OutT>
__global__ void __launch_bounds__(128, 2)
gemm_f16(const __half* __restrict__ A, const __half* __restrict__ W,
         const float* __restrict__ bias0, const float* __restrict__ bias1,
         const float* __restrict__ bias2, int nb1, int nb2,
         OutT* __restrict__ C, int N, int K)
{
    extern __shared__ __align__(16) char smem[];
    const uint32_t sb = smem_to_u32(smem);
    const int tid = threadIdx.x;
    const int lane = tid & 31;
    const int warp = tid >> 5;
    const int bm = blockIdx.y * 128;
    const int bn = blockIdx.x * 128;
    const int wm0 = (warp & 1) * 64;
    const int wn0 = (warp >> 1) * 64;

    float acc[4][8][4];
#pragma unroll
    for (int i = 0; i < 4; i++)
#pragma unroll
        for (int j = 0; j < 8; j++)
#pragma unroll
            for (int r = 0; r < 4; r++) acc[i][j][r] = 0.f;

    const int lrow = tid >> 3;     // 0..15
    const int lq   = tid & 7;      // quarter 0..7 within 128B row

    auto load_chunk = [&](int stage, int ck) {
        const uint32_t stb = sb + stage * STAGEB;
#pragma unroll
        for (int l = 0; l < 8; l++) {
            int row = lrow + l * 16;
            uint32_t dst = stb + row * 128 + ((lq ^ (row & 7)) << 4);
            const size_t kof = (size_t)ck * GBK + lq * 8;
            cp16(dst,         A + (size_t)(bm + row) * K + kof);
            cp16(dst + TILEB, W + (size_t)(bn + row) * K + kof);
        }
    };

    const int arow[4] = {wm0 + 0 * 16 + (lane & 15), wm0 + 1 * 16 + (lane & 15),
                         wm0 + 2 * 16 + (lane & 15), wm0 + 3 * 16 + (lane & 15)};
    const int ahalf = lane >> 4;
    const int brow[4] = {wn0 + 0 * 16 + (lane & 7) + ((lane >> 4) << 3),
                         wn0 + 1 * 16 + (lane & 7) + ((lane >> 4) << 3),
                         wn0 + 2 * 16 + (lane & 7) + ((lane >> 4) << 3),
                         wn0 + 3 * 16 + (lane & 7) + ((lane >> 4) << 3)};
    const int bhalf = (lane >> 3) & 1;

    auto compute = [&](int stage) {
        const uint32_t tA = sb + stage * STAGEB;
        const uint32_t tW = tA + TILEB;
#pragma unroll
        for (int ks = 0; ks < 4; ks++) {
            uint32_t a[4][4], b[4][4];
#pragma unroll
            for (int rb = 0; rb < 4; rb++) {
                int r = arow[rb];
                uint32_t q = (uint32_t)((2 * ks + ahalf) ^ (r & 7));
                ldx4(a[rb], tA + (uint32_t)r * 128 + (q << 4));
            }
#pragma unroll
            for (int hb = 0; hb < 4; hb++) {
                int r = brow[hb];
                uint32_t q = (uint32_t)((2 * ks + bhalf) ^ (r & 7));
                ldx4(b[hb], tW + (uint32_t)r * 128 + (q << 4));
            }
#pragma unroll
            for (int rb = 0; rb < 4; rb++) {
#pragma unroll
                for (int nb = 0; nb < 8; nb++) {
                    mma16816(acc[rb][nb], a[rb], &b[nb >> 1][(nb & 1) * 2]);
                }
            }
        }
    };

    const int nchunk = K / GBK;   // 16
    load_chunk(0, 0); cp_commit();
    load_chunk(1, 1); cp_commit();
    for (int c = 0; c < nchunk; c++) {
        if (c == nchunk - 1) cp_wait0(); else cp_wait1();
        __syncthreads();
        if (c + 2 < nchunk) { load_chunk((c + 2) % NSTG, c + 2); cp_commit(); }
        compute(c % NSTG);
    }

    // bias segment select (bn is segment-uniform: boundaries are multiples of 128)
    const float* bp; int segbase;
    if (bn < nb1)      { bp = bias0; segbase = 0;   }
    else if (bn < nb2) { bp = bias1; segbase = nb1; }
    else               { bp = bias2; segbase = nb2; }

    // epilogue
#pragma unroll
    for (int rb = 0; rb < 4; rb++) {
#pragma unroll
        for (int nb = 0; nb < 8; nb++) {
            int row = bm + wm0 + rb * 16 + (lane >> 2);
            int col = bn + wn0 + nb * 8 + (lane & 3) * 2;
            float b0 = bp[col - segbase], b1 = bp[col - segbase + 1];
            float o0 = acc[rb][nb][0] + b0, o1 = acc[rb][nb][1] + b1;
            float o2 = acc[rb][nb][2] + b0, o3 = acc[rb][nb][3] + b1;
            if constexpr (sizeof(OutT) == 2) {
                __half2 h0 = __floats2half2_rn(o0, o1);
                __half2 h1 = __floats2half2_rn(o2, o3);
                *(__half2*)((__half*)C + (size_t)row * N + col)       = h0;
                *(__half2*)((__half*)C + (size_t)(row + 8) * N + col) = h1;
            } else {
                float2 v0 = {o0, o1}, v1 = {o2, o3};
                *(float2*)((float*)C + (size_t)row * N + col)       = v0;
                *(float2*)((float*)C + (size_t)(row + 8) * N + col) = v1;
            }
        }
    }
}

// ------------------------- per-token head-mixing attention ------------------
// qkv row layout: [q(4096) | k(1024) | v(1024)] per token (stride NQKV).
#define KSTR 68    // k smem row stride (floats): 68 mod 32 = 4 -> conflict-free f4
__global__ void __launch_bounds__(256)
attn_kernel(const __half* __restrict__ gqkv, __half* __restrict__ gy)
{
    const int tok = blockIdx.x;
    const int t = threadIdx.x;
    const __half* base = gqkv + (size_t)tok * NQKV;

    __shared__ __align__(16) float qs[QN * HN * DH];
    __shared__ __align__(16) float ks[HN * KSTR];
    __shared__ __align__(16) float vs[HN * DH];
    __shared__ float sc[QN][HN][HN];
    __shared__ float ps[HN][HN];

    {
        const uint4* qg = (const uint4*)base;
#pragma unroll
        for (int l = 0; l < 2; l++) {
            uint4 p = qg[t + l * 256];
            const __half2* hp = (const __half2*)&p;
            float* dst = qs + (t + l * 256) * 8;
#pragma unroll
            for (int j = 0; j < 4; j++) {
                float2 f = __half22float2(hp[j]);
                dst[2 * j] = f.x; dst[2 * j + 1] = f.y;
            }
        }
    }
    if (t < 128) {
        uint4 p = ((const uint4*)(base + QCOLS))[t];
        const __half2* hp = (const __half2*)&p;
        int g = t >> 3, d = (t * 8) & 63;
        float* kr = ks + g * KSTR + d;
#pragma unroll
        for (int j = 0; j < 4; j++) {
            float2 f = __half22float2(hp[j]);
            kr[2 * j] = f.x; kr[2 * j + 1] = f.y;
        }
    } else {
        int tt = t - 128;
        uint4 p = ((const uint4*)(base + QCOLS + EDIM))[tt];
        const __half2* hp = (const __half2*)&p;
        int g = tt >> 3, d = (tt * 8) & 63;
        float* vr = vs + g * DH + d;
#pragma unroll
        for (int j = 0; j < 4; j++) {
            float2 f = __half22float2(hp[j]);
            vr[2 * j] = f.x; vr[2 * j + 1] = f.y;
        }
    }
    __syncthreads();

    const float scale = 0.125f;
#pragma unroll
    for (int l = 0; l < 4; l++) {
        int e = t + l * 256;
        int qq = e >> 8, h = (e >> 4) & 15, g = e & 15;
        const float4* qp4 = (const float4*)(qs + (qq * HN + h) * DH);
        const float4* kp4 = (const float4*)(ks + g * KSTR);
        float s_ = 0.f;
#pragma unroll
        for (int d = 0; d < 16; d++) {
            float4 a = qp4[d], b = kp4[d];
            s_ += a.x * b.x + a.y * b.y + a.z * b.z + a.w * b.w;
        }
        sc[qq][h][g] = s_ * scale;
    }
    __syncthreads();

    if (t < 64) {
        int qq = t >> 4, h = t & 15;
        float* row = sc[qq][h];
        float m = row[0];
#pragma unroll
        for (int g = 1; g < 16; g++) m = fmaxf(m, row[g]);
        float ssum = 0.f;
#pragma unroll
        for (int g = 0; g < 16; g++) { float ex = __expf(row[g] - m); row[g] = ex; ssum += ex; }
        float inv = 1.f / ssum;
#pragma unroll
        for (int g = 0; g < 16; g++) row[g] *= inv;
    }
    __syncthreads();

    {
        int h = t >> 4, g = t & 15;
        ps[h][g] = sc[0][h][g] + sc[1][h][g] + sc[2][h][g] + sc[3][h][g];
    }
    __syncthreads();

    const int b = tok >> 11, s = tok & 2047;
    {
        int h = t >> 4;
        int d0 = (t * 4) & 63;
        const float4* vp4 = (const float4*)vs;   // 16 float4 per row
        float4 o = {0.f, 0.f, 0.f, 0.f};
#pragma unroll
        for (int g = 0; g < 16; g++) {
            float p = ps[h][g];
            float4 vv = vp4[g * 16 + (d0 >> 2)];
            o.x = fmaf(p, vv.x, o.x); o.y = fmaf(p, vv.y, o.y);
            o.z = fmaf(p, vv.z, o.z); o.w = fmaf(p, vv.w, o.w);
        }
        __half2 h0 = __floats2half2_rn(o.x, o.y);
        __half2 h1 = __floats2half2_rn(o.z, o.w);
        size_t oi = (((size_t)b * HN + h) * SEQ + s) * DH + d0;
        *(__half2*)(gy + oi)     = h0;
        *(__half2*)(gy + oi + 2) = h1;
    }
}

// ------------------------- launch -------------------------------------------
extern "C" void kernel_launch(void* const* d_in, const int* in_sizes, int n_in,
                              void* d_out, int out_size)
{
    const float* x  = (const float*)d_in[0];
    const float* Wq = (const float*)d_in[1];
    const float* bq = (const float*)d_in[2];
    const float* Wk = (const float*)d_in[3];
    const float* bk = (const float*)d_in[4];
    const float* Wv = (const float*)d_in[5];
    const float* bv = (const float*)d_in[6];
    const float* Wo = (const float*)d_in[7];
    const float* bo = (const float*)d_in[8];
    float* out = (float*)d_out;
    (void)in_sizes; (void)n_in; (void)out_size;

    __half *qkv, *xf, *gy, *wqkv, *wo;
    cudaGetSymbolAddress((void**)&qkv, g_qkv);
    cudaGetSymbolAddress((void**)&xf, g_xf);
    cudaGetSymbolAddress((void**)&gy, g_y);
    cudaGetSymbolAddress((void**)&wqkv, g_wqkv);
    cudaGetSymbolAddress((void**)&wo, g_wo);

    cudaFuncSetAttribute(gemm_f16<float>,  cudaFuncAttributeMaxDynamicSharedMemorySize, GSMEM);
    cudaFuncSetAttribute(gemm_f16<__half>, cudaFuncAttributeMaxDynamicSharedMemorySize, GSMEM);

    // 1) fused fp32 -> fp16 conversions (x + packed QKV weights + Wo)
    conv_all<<<(S_ALL + 255) / 256, 256>>>(x, Wq, Wk, Wv, Wo, xf, wqkv, wo);

    // 2) fused QKV projection (N = 6144), bias segment-selected per CTA
    gemm_f16<__half><<<dim3(NQKV / 128, NTOK / 128), 128, GSMEM>>>(
        xf, wqkv, bq, bk, bv, QCOLS, QCOLS + EDIM, qkv, NQKV, EDIM);

    // 3) per-token attention -> y fp16 ((B,H,S,D) flat == (B,S,E) flat)
    attn_kernel<<<NTOK, 256>>>(qkv, gy);

    // 4) output projection (fp32 out)
    gemm_f16<float><<<dim3(EDIM / 128, NTOK / 128), 128, GSMEM>>>(
        gy, wo, bo, bo, bo, 1 << 30, 1 << 30, out, EDIM, EDIM);
}